// round 8
// baseline (speedup 1.0000x reference)
#include <cuda_runtime.h>
#include <cuda.h>
#include <cuda_bf16.h>
#include <cuda_fp16.h>
#include <cuda_fp8.h>
#include <cstdint>

// Shapes (fixed): B=4, S=2048, D=1024
#define BB 4
#define SS 2048
#define DD 1024
#define MQKV (BB * SS)            // 8192

// ---- GEMM tile: 256x128, BK=32, 4-deep TMA pipeline, SW64 (64B rows) ------
#define TM_ 256
#define TN_ 128
#define BK 32
#define A16_B (256 * 64)          // fp16 A tile: 256 rows x 64B (32 halves)
#define A8_B  (256 * 64)          // fp8  A tile: 256 rows x 64B ([hi|lo] x32)
#define B16_B (128 * 64)
#define B8_B  (128 * 64)
#define STAGE_B (A16_B + A8_B + B16_B + B8_B)    // 49152
#define NSTAGE 4
#define SMEM_TOTAL (1024 + NSTAGE * STAGE_B)     // 197632
#define NT 256                    // 8 warps

// ---------------- scratch (device globals; allocation-free rule) -----------
__device__ __align__(256) __half        g_x16[(size_t)MQKV * DD];
__device__ __align__(256) unsigned char g_x8[(size_t)MQKV * 2 * DD];
__device__ __align__(256) __half        g_W16[(size_t)3 * DD * DD];      // W^T planes
__device__ __align__(256) unsigned char g_W8[(size_t)3 * DD * 2 * DD];
__device__ __align__(256) float         g_F[(size_t)MQKV * DD];          // fp32 staging (V)
__device__ __align__(256) __half        g_QK16[2][(size_t)MQKV * DD];    // Q,K fp16
__device__ __align__(256) unsigned char g_QK8[2][(size_t)MQKV * 2 * DD]; // Q,K fp8 packs
__device__ __align__(256) __half        g_V16[(size_t)DD * MQKV];        // V^T fp16
__device__ __align__(256) unsigned char g_V8[(size_t)DD * 2 * MQKV];
__device__ __align__(256) __half        g_P16[(size_t)MQKV * SS];        // exp(S) fp16
__device__ __align__(256) unsigned char g_P8[(size_t)MQKV * 2 * SS];
__device__ __align__(256) float         g_RS[MQKV];                      // row sums

// ---------------- PTX helpers ----------------------------------------------
__device__ __forceinline__ uint32_t smem_u32(const void* p) {
    uint32_t a;
    asm("{ .reg .u64 t; cvta.to.shared.u64 t, %1; cvt.u32.u64 %0, t; }"
        : "=r"(a) : "l"(p));
    return a;
}
#define LDSM4(r, addr)                                                      \
    asm volatile("ldmatrix.sync.aligned.m8n8.x4.shared.b16 {%0,%1,%2,%3}, [%4];" \
        : "=r"((r)[0]), "=r"((r)[1]), "=r"((r)[2]), "=r"((r)[3]) : "r"(addr))

#define MMA16(c, a, b0, b1)                                                 \
    asm volatile("mma.sync.aligned.m16n8k16.row.col.f32.f16.f16.f32 "       \
        "{%0,%1,%2,%3}, {%4,%5,%6,%7}, {%8,%9}, {%0,%1,%2,%3};"             \
        : "+f"((c)[0]), "+f"((c)[1]), "+f"((c)[2]), "+f"((c)[3])            \
        : "r"((a)[0]), "r"((a)[1]), "r"((a)[2]), "r"((a)[3]),               \
          "r"(b0), "r"(b1))

#define MMA8(c, a, b0, b1)                                                  \
    asm volatile("mma.sync.aligned.m16n8k32.row.col.f32.e5m2.e5m2.f32 "     \
        "{%0,%1,%2,%3}, {%4,%5,%6,%7}, {%8,%9}, {%0,%1,%2,%3};"             \
        : "+f"((c)[0]), "+f"((c)[1]), "+f"((c)[2]), "+f"((c)[3])            \
        : "r"((a)[0]), "r"((a)[1]), "r"((a)[2]), "r"((a)[3]),               \
          "r"(b0), "r"(b1))

__device__ __forceinline__ void tma2d(uint32_t dst, const void* map,
                                      int x, int y, uint32_t mb) {
    asm volatile(
        "cp.async.bulk.tensor.2d.shared::cta.global.tile.mbarrier::complete_tx::bytes "
        "[%0], [%1, {%2, %3}], [%4];"
        :: "r"(dst), "l"(map), "r"(x), "r"(y), "r"(mb) : "memory");
}
#define MB_INIT(mb, c) \
    asm volatile("mbarrier.init.shared.b64 [%0], %1;" :: "r"(mb), "r"(c) : "memory")
#define MB_EXPECT(mb, bytes) \
    asm volatile("mbarrier.arrive.expect_tx.shared.b64 _, [%0], %1;" \
                 :: "r"(mb), "r"(bytes) : "memory")
#define MB_WAIT(mb, ph) do {                                               \
    asm volatile("{\n\t.reg .pred P;\n\t"                                  \
        "WL%=:\n\t"                                                        \
        "mbarrier.try_wait.parity.acquire.cta.shared::cta.b64 P, [%0], %1;\n\t" \
        "@!P bra WL%=;\n\t}"                                               \
        :: "r"(mb), "r"(ph) : "memory");                                   \
} while (0)

__device__ __forceinline__ unsigned short fp8x2(float a, float b) {
    float2 f; f.x = a; f.y = b;
    return (unsigned short)__nv_cvt_float2_to_fp8x2(f, __NV_SATFINITE, __NV_E5M2);
}

// ---------------------------------------------------------------------------
// fp16 + fp8-cross GEMM with deep TMA pipeline.
//   acc = Ah@Bh^T (fp16 MMA) + [Ah*2^-4|Al*2^4] @ [Bl*2^4|Bh*2^-4]^T (e5m2 MMA)
// EPI=1 (projections, z in {0,1,2}): z0=Q (A-role split out), z1=K (B-role),
//                                    z2=fp32 C (V staging)
// EPI=2 (scores): p = expf(acc*alpha), A-role split out
// EPI=3 (AV): o = acc / RS[z*SS+row], fp32 out
// Grid (N/128, M/256, z). 256 threads, 8 warps of 64x64.
// ---------------------------------------------------------------------------
template <int EPI>
__global__ __launch_bounds__(NT, 1)
void mma_gemm(const __grid_constant__ CUtensorMap mA16,
              const __grid_constant__ CUtensorMap mA8,
              const __grid_constant__ CUtensorMap mB16,
              const __grid_constant__ CUtensorMap mB8,
              float* __restrict__ C,
              __half* __restrict__ C16, unsigned char* __restrict__ C8,
              const float* __restrict__ RS,
              int K, int ldc, size_t strideC,
              int zRowA, int zRowB, int zColB, float alpha)
{
    extern __shared__ char smem[];
    const uint32_t sbase = smem_u32(smem);
    const uint32_t bufs  = (sbase + 1023u) & ~1023u;
    const uint32_t mbar  = sbase;
    const int tid  = threadIdx.x;
    const int lane = tid & 31, wid = tid >> 5;
    const int bz = blockIdx.z;
    const int tileM = blockIdx.y * TM_;
    const int tileN = blockIdx.x * TN_;
    const int rowA0 = tileM + bz * zRowA;
    const int rowB0 = tileN + bz * zRowB;
    const int colB0 = bz * zColB;

    if (tid == 0) {
        #pragma unroll
        for (int i = 0; i < NSTAGE; i++) MB_INIT(mbar + 8 * i, 1);
    }
    __syncthreads();

    const int nst = K / BK;
    auto issue = [&](int s) {
        const uint32_t buf = bufs + (uint32_t)(s & (NSTAGE - 1)) * STAGE_B;
        const uint32_t mb  = mbar + (uint32_t)(s & (NSTAGE - 1)) * 8;
        MB_EXPECT(mb, STAGE_B);
        tma2d(buf,                   &mA16, s * 32,                rowA0, mb);
        tma2d(buf + A16_B,           &mA8,  s * 64,                rowA0, mb);
        tma2d(buf + A16_B + A8_B,    &mB16, s * 32 + colB0,        rowB0, mb);
        tma2d(buf + A16_B + A8_B + B16_B, &mB8, s * 64 + 2 * colB0, rowB0, mb);
    };
    if (tid == 0) { issue(0); issue(1); issue(2); }

    const int wm = (wid >> 1) * 64;
    const int wn = (wid & 1) * 64;

    // ldmatrix lane addressing; SW64 xor = ((row>>1)&3)<<4; rows are 64B in
    // BOTH the fp16 and fp8 tiles, so offsets/xors are shared.
    uint32_t aoff[4], axor[4], boff[4], bxor[4];
    {
        const int arl = wm + (lane & 15);
        const int brl = wn + (lane & 7) + ((lane >> 4) * 8);
        #pragma unroll
        for (int i = 0; i < 4; i++) {
            int ar = arl + i * 16;
            aoff[i] = (uint32_t)(ar * 64);
            axor[i] = (uint32_t)(((ar >> 1) & 3) << 4);
            int br = brl + i * 16;
            boff[i] = (uint32_t)(br * 64);
            bxor[i] = (uint32_t)(((br >> 1) & 3) << 4);
        }
    }
    const uint32_t a_colb = (uint32_t)((lane >> 4) * 16);
    const uint32_t b_colb = (uint32_t)(((lane >> 3) & 1) * 16);

    float acc[4][8][4];
    #pragma unroll
    for (int i = 0; i < 4; i++)
        #pragma unroll
        for (int j = 0; j < 8; j++)
            #pragma unroll
            for (int r = 0; r < 4; r++) acc[i][j][r] = 0.0f;

    for (int s = 0; s < nst; s++) {
        const uint32_t buf = bufs + (uint32_t)(s & (NSTAGE - 1)) * STAGE_B;
        MB_WAIT(mbar + (uint32_t)(s & (NSTAGE - 1)) * 8, (uint32_t)((s >> 2) & 1));
        if (tid == 0 && s + 3 < nst) issue(s + 3);

        const uint32_t A16b = buf;
        const uint32_t A8b  = buf + A16_B;
        const uint32_t B16b = buf + A16_B + A8_B;
        const uint32_t B8b  = buf + A16_B + A8_B + B16_B;

        // ---- fp16 main terms: 2 x k16 ----
        #pragma unroll
        for (int ks = 0; ks < 2; ks++) {
            const uint32_t kb = (uint32_t)(ks * 32);
            uint32_t a[4][4], b[4][4];
            #pragma unroll
            for (int mt = 0; mt < 4; mt++)
                LDSM4(a[mt], A16b + aoff[mt] + ((kb + a_colb) ^ axor[mt]));
            #pragma unroll
            for (int j = 0; j < 4; j++)
                LDSM4(b[j], B16b + boff[j] + ((kb + b_colb) ^ bxor[j]));
            #pragma unroll
            for (int mt = 0; mt < 4; mt++)
                #pragma unroll
                for (int j = 0; j < 4; j++) {
                    MMA16(acc[mt][2 * j],     a[mt], b[j][0], b[j][1]);
                    MMA16(acc[mt][2 * j + 1], a[mt], b[j][2], b[j][3]);
                }
        }
        // ---- fp8 cross terms: 2 x 32-byte halves (each = one k32 e5m2) ----
        #pragma unroll
        for (int hb = 0; hb < 2; hb++) {
            const uint32_t kb = (uint32_t)(hb * 32);
            uint32_t a[4][4], b[4][4];
            #pragma unroll
            for (int mt = 0; mt < 4; mt++)
                LDSM4(a[mt], A8b + aoff[mt] + ((kb + a_colb) ^ axor[mt]));
            #pragma unroll
            for (int j = 0; j < 4; j++)
                LDSM4(b[j], B8b + boff[j] + ((kb + b_colb) ^ bxor[j]));
            #pragma unroll
            for (int mt = 0; mt < 4; mt++)
                #pragma unroll
                for (int j = 0; j < 4; j++) {
                    MMA8(acc[mt][2 * j],     a[mt], b[j][0], b[j][1]);
                    MMA8(acc[mt][2 * j + 1], a[mt], b[j][2], b[j][3]);
                }
        }
        __syncthreads();
    }

    // ---- epilogue ----
    const int er = lane >> 2;
    const int ec = (lane & 3) * 2;
    const bool fp32_path = (EPI == 3) || (EPI == 1 && bz == 2);
    float* Cz = (EPI == 3) ? C + (size_t)bz * strideC : C;
    __half* C16z = C16 + (size_t)bz * strideC;
    unsigned char* C8z = C8 + (size_t)bz * 2 * strideC;
    const bool Arole = (EPI == 2) || (EPI == 1 && bz == 0);
    const int ld8 = 2 * ldc;
    const float* rs = (EPI == 3) ? (RS + (size_t)bz * SS) : nullptr;

    #pragma unroll
    for (int mt = 0; mt < 4; mt++) {
        const int rloc = tileM + wm + mt * 16 + er;
        float inv0 = 0.f, inv1 = 0.f;
        if (EPI == 3) { inv0 = 1.0f / rs[rloc]; inv1 = 1.0f / rs[rloc + 8]; }
        #pragma unroll
        for (int j = 0; j < 8; j++) {
            const int c0 = tileN + wn + j * 8 + ec;
            float v0 = acc[mt][j][0] * alpha, v1 = acc[mt][j][1] * alpha;
            float v2 = acc[mt][j][2] * alpha, v3 = acc[mt][j][3] * alpha;
            if (EPI == 2) {
                v0 = __expf(v0); v1 = __expf(v1);
                v2 = __expf(v2); v3 = __expf(v3);
            }
            if (EPI == 3) { v0 *= inv0; v1 *= inv0; v2 *= inv1; v3 *= inv1; }
            if (fp32_path) {
                *reinterpret_cast<float2*>(&Cz[(size_t)rloc * ldc + c0]) =
                    make_float2(v0, v1);
                *reinterpret_cast<float2*>(&Cz[(size_t)(rloc + 8) * ldc + c0]) =
                    make_float2(v2, v3);
            } else {
                const size_t bcol = (size_t)((c0 >> 5) << 6) + (c0 & 31);
                // row rloc
                __half2 h0 = __floats2half2_rn(v0, v1);
                float h0x = __low2float(h0), h0y = __high2float(h0);
                *reinterpret_cast<__half2*>(&C16z[(size_t)rloc * ldc + c0]) = h0;
                unsigned short hi0 = fp8x2(h0x * 0.0625f, h0y * 0.0625f);
                unsigned short lo0 = fp8x2((v0 - h0x) * 16.f, (v1 - h0y) * 16.f);
                size_t b0 = (size_t)rloc * ld8 + bcol;
                *reinterpret_cast<unsigned short*>(&C8z[b0 + (Arole ? 0 : 32)]) = hi0;
                *reinterpret_cast<unsigned short*>(&C8z[b0 + (Arole ? 32 : 0)]) = lo0;
                // row rloc+8
                __half2 h1 = __floats2half2_rn(v2, v3);
                float h1x = __low2float(h1), h1y = __high2float(h1);
                *reinterpret_cast<__half2*>(&C16z[(size_t)(rloc + 8) * ldc + c0]) = h1;
                unsigned short hi1 = fp8x2(h1x * 0.0625f, h1y * 0.0625f);
                unsigned short lo1 = fp8x2((v2 - h1x) * 16.f, (v3 - h1y) * 16.f);
                size_t b1 = (size_t)(rloc + 8) * ld8 + bcol;
                *reinterpret_cast<unsigned short*>(&C8z[b1 + (Arole ? 0 : 32)]) = hi1;
                *reinterpret_cast<unsigned short*>(&C8z[b1 + (Arole ? 32 : 0)]) = lo1;
            }
        }
    }
}

// ---------------------------------------------------------------------------
// fp32 -> fp16 + fp8 pack (A-role), elementwise (4 elems/thread)
// ---------------------------------------------------------------------------
__global__ __launch_bounds__(256)
void splitA_kernel(const float* __restrict__ in,
                   __half* __restrict__ o16, unsigned char* __restrict__ o8,
                   int K, size_t n4)
{
    size_t i = (size_t)blockIdx.x * blockDim.x + threadIdx.x;
    if (i >= n4) return;
    float4 v = reinterpret_cast<const float4*>(in)[i];
    size_t e = i * 4;
    size_t r = e / (size_t)K;
    int    c = (int)(e % (size_t)K);
    __half2 h01 = __floats2half2_rn(v.x, v.y);
    __half2 h23 = __floats2half2_rn(v.z, v.w);
    *reinterpret_cast<__half2*>(o16 + e)     = h01;
    *reinterpret_cast<__half2*>(o16 + e + 2) = h23;
    float hx = __low2float(h01), hy = __high2float(h01);
    float hz = __low2float(h23), hw = __high2float(h23);
    unsigned int hi = (unsigned int)fp8x2(hx * 0.0625f, hy * 0.0625f)
                    | ((unsigned int)fp8x2(hz * 0.0625f, hw * 0.0625f) << 16);
    unsigned int lo = (unsigned int)fp8x2((v.x - hx) * 16.f, (v.y - hy) * 16.f)
                    | ((unsigned int)fp8x2((v.z - hz) * 16.f, (v.w - hw) * 16.f) << 16);
    size_t b = r * (size_t)(2 * K) + (size_t)((c >> 5) << 6) + (c & 31);
    *reinterpret_cast<unsigned int*>(&o8[b])      = hi;   // A-role: hi first
    *reinterpret_cast<unsigned int*>(&o8[b + 32]) = lo;
}

// ---------------------------------------------------------------------------
// fp32 [R,C] -> transposed fp16 [C,R] + fp8 pack (B-role)
// ---------------------------------------------------------------------------
__global__ __launch_bounds__(256)
void tsplitB_kernel(const float* __restrict__ in,
                    __half* __restrict__ o16, unsigned char* __restrict__ o8,
                    int R, int C)
{
    __shared__ float tile[32][33];
    const int c0 = blockIdx.x * 32, r0 = blockIdx.y * 32;
    const int tx = threadIdx.x, ty = threadIdx.y;   // 32 x 8
    #pragma unroll
    for (int j = 0; j < 32; j += 8)
        tile[ty + j][tx] = in[(size_t)(r0 + ty + j) * C + c0 + tx];
    __syncthreads();
    #pragma unroll
    for (int j = 0; j < 32; j += 8) {
        float v = tile[tx][ty + j];
        __half h = __float2half_rn(v);
        float hf = __half2float(h);
        int orow = c0 + ty + j;
        int ocol = r0 + tx;
        o16[(size_t)orow * R + ocol] = h;
        size_t b = (size_t)orow * (size_t)(2 * R)
                 + (size_t)((ocol >> 5) << 6) + (ocol & 31);
        o8[b]      = (unsigned char)__nv_cvt_float_to_fp8(
                         (v - hf) * 16.f, __NV_SATFINITE, __NV_E5M2);  // B-role: lo first
        o8[b + 32] = (unsigned char)__nv_cvt_float_to_fp8(
                         hf * 0.0625f, __NV_SATFINITE, __NV_E5M2);
    }
}

// ---------------------------------------------------------------------------
// Row sums of exp(S) from fp16 P
// ---------------------------------------------------------------------------
__global__ __launch_bounds__(256)
void rowsum_kernel(const __half* __restrict__ P16, float* __restrict__ RS)
{
    __shared__ float sh[8];
    const size_t base = (size_t)blockIdx.x * SS;
    const int tid = threadIdx.x;
    const __half2* ph = reinterpret_cast<const __half2*>(P16 + base);
    float s = 0.0f;
    #pragma unroll
    for (int i = 0; i < 4; i++) {
        float2 a = __half22float2(ph[tid + i * 256]);
        s += a.x + a.y;
    }
    #pragma unroll
    for (int o = 16; o > 0; o >>= 1) s += __shfl_xor_sync(~0u, s, o);
    if ((tid & 31) == 0) sh[tid >> 5] = s;
    __syncthreads();
    if (tid < 32) {
        s = (tid < 8) ? sh[tid] : 0.0f;
        #pragma unroll
        for (int o = 4; o > 0; o >>= 1) s += __shfl_xor_sync(~0u, s, o);
        if (tid == 0) RS[blockIdx.x] = s;
    }
}

// ---------------------------------------------------------------------------
// Host: tensor-map builders
// ---------------------------------------------------------------------------
typedef CUresult (*PFN_TMAPENC)(CUtensorMap*, CUtensorMapDataType, cuuint32_t,
                                void*, const cuuint64_t*, const cuuint64_t*,
                                const cuuint32_t*, const cuuint32_t*,
                                CUtensorMapInterleave, CUtensorMapSwizzle,
                                CUtensorMapL2promotion, CUtensorMapFloatOOBfill);

static void map16(PFN_TMAPENC enc, CUtensorMap* m, void* base,
                  unsigned long long cols, unsigned long long rows,
                  unsigned box_rows)
{
    cuuint64_t dims[2]    = {cols, rows};
    cuuint64_t strides[1] = {cols * 2};
    cuuint32_t box[2]     = {32, box_rows};
    cuuint32_t es[2]      = {1, 1};
    enc(m, CU_TENSOR_MAP_DATA_TYPE_FLOAT16, 2, base, dims, strides, box, es,
        CU_TENSOR_MAP_INTERLEAVE_NONE, CU_TENSOR_MAP_SWIZZLE_64B,
        CU_TENSOR_MAP_L2_PROMOTION_L2_128B, CU_TENSOR_MAP_FLOAT_OOB_FILL_NONE);
}
static void map8(PFN_TMAPENC enc, CUtensorMap* m, void* base,
                 unsigned long long cols_bytes, unsigned long long rows,
                 unsigned box_rows)
{
    cuuint64_t dims[2]    = {cols_bytes, rows};
    cuuint64_t strides[1] = {cols_bytes};
    cuuint32_t box[2]     = {64, box_rows};
    cuuint32_t es[2]      = {1, 1};
    enc(m, CU_TENSOR_MAP_DATA_TYPE_UINT8, 2, base, dims, strides, box, es,
        CU_TENSOR_MAP_INTERLEAVE_NONE, CU_TENSOR_MAP_SWIZZLE_64B,
        CU_TENSOR_MAP_L2_PROMOTION_L2_128B, CU_TENSOR_MAP_FLOAT_OOB_FILL_NONE);
}

extern "C" void kernel_launch(void* const* d_in, const int* in_sizes, int n_in,
                              void* d_out, int out_size)
{
    const float* x  = (const float*)d_in[0];
    const float* WQ = (const float*)d_in[1];
    const float* WK = (const float*)d_in[2];
    const float* WV = (const float*)d_in[3];
    float* out = (float*)d_out;

    __half *x16, *W16, *QK16, *V16, *P16;
    unsigned char *x8, *W8, *QK8, *V8, *P8;
    float *F, *RS;
    cudaGetSymbolAddress((void**)&x16, g_x16);
    cudaGetSymbolAddress((void**)&x8,  g_x8);
    cudaGetSymbolAddress((void**)&W16, g_W16);
    cudaGetSymbolAddress((void**)&W8,  g_W8);
    cudaGetSymbolAddress((void**)&F,   g_F);
    cudaGetSymbolAddress((void**)&QK16, g_QK16);
    cudaGetSymbolAddress((void**)&QK8,  g_QK8);
    cudaGetSymbolAddress((void**)&V16, g_V16);
    cudaGetSymbolAddress((void**)&V8,  g_V8);
    cudaGetSymbolAddress((void**)&P16, g_P16);
    cudaGetSymbolAddress((void**)&P8,  g_P8);
    cudaGetSymbolAddress((void**)&RS,  g_RS);

    const size_t nQK = (size_t)MQKV * DD;
    const size_t nW  = (size_t)DD * DD;

    PFN_TMAPENC enc = nullptr;
    cudaDriverEntryPointQueryResult qres;
    cudaGetDriverEntryPoint("cuTensorMapEncodeTiled", (void**)&enc,
                            cudaEnableDefault, &qres);

    CUtensorMap mX16, mX8, mW16v, mW8v, mQ16, mQ8, mK16, mK8, mP16v, mP8v, mV16v, mV8v;
    map16(enc, &mX16, x16, DD, MQKV, 256);
    map8 (enc, &mX8,  x8,  2 * DD, MQKV, 256);
    map16(enc, &mW16v, W16, DD, 3 * DD, 128);
    map8 (enc, &mW8v,  W8,  2 * DD, 3 * DD, 128);
    map16(enc, &mQ16, QK16, DD, MQKV, 256);
    map8 (enc, &mQ8,  QK8,  2 * DD, MQKV, 256);
    map16(enc, &mK16, QK16 + nQK, DD, MQKV, 128);
    map8 (enc, &mK8,  QK8 + 2 * nQK, 2 * DD, MQKV, 128);
    map16(enc, &mP16v, P16, SS, MQKV, 256);
    map8 (enc, &mP8v,  P8,  2 * SS, MQKV, 256);
    map16(enc, &mV16v, V16, MQKV, DD, 128);
    map8 (enc, &mV8v,  V8,  2 * MQKV, DD, 128);

    cudaFuncSetAttribute(mma_gemm<1>, cudaFuncAttributeMaxDynamicSharedMemorySize, SMEM_TOTAL);
    cudaFuncSetAttribute(mma_gemm<2>, cudaFuncAttributeMaxDynamicSharedMemorySize, SMEM_TOTAL);
    cudaFuncSetAttribute(mma_gemm<3>, cudaFuncAttributeMaxDynamicSharedMemorySize, SMEM_TOTAL);

    const size_t n4x = (size_t)MQKV * DD / 4;
    dim3 tb(32, 8);

    // 1) input conversions
    splitA_kernel<<<(unsigned)((n4x + 255) / 256), 256>>>(x, x16, x8, DD, n4x);
    tsplitB_kernel<<<dim3(DD / 32, DD / 32), tb>>>(WQ, W16 + 0 * nW, W8 + 0 * 2 * nW, DD, DD);
    tsplitB_kernel<<<dim3(DD / 32, DD / 32), tb>>>(WK, W16 + 1 * nW, W8 + 1 * 2 * nW, DD, DD);
    tsplitB_kernel<<<dim3(DD / 32, DD / 32), tb>>>(WV, W16 + 2 * nW, W8 + 2 * 2 * nW, DD, DD);

    // 2) all 3 projections (z: 0=Q A-role, 1=K B-role, 2=V fp32 staging)
    dim3 gp(DD / TN_, MQKV / TM_, 3);
    mma_gemm<1><<<gp, NT, SMEM_TOTAL>>>(mX16, mX8, mW16v, mW8v,
                                        F, QK16, QK8, nullptr,
                                        DD, DD, nQK, 0, DD, 0, 1.0f);
    tsplitB_kernel<<<dim3(DD / 32, MQKV / 32), tb>>>(F, V16, V8, MQKV, DD);

    // 3) scores + exp fused: P = exp(Q @ K^T / 32), A-role split out
    dim3 gs(SS / TN_, SS / TM_, BB);
    mma_gemm<2><<<gs, NT, SMEM_TOTAL>>>(mQ16, mQ8, mK16, mK8,
                                        nullptr, P16, P8, nullptr,
                                        DD, SS, (size_t)SS * SS, SS, SS, 0,
                                        1.0f / 32.0f);

    // 4) row sums
    rowsum_kernel<<<MQKV, 256>>>(P16, RS);

    // 5) O = (P @ V^T-rows) / rowsum
    dim3 go(DD / TN_, SS / TM_, BB);
    mma_gemm<3><<<go, NT, SMEM_TOTAL>>>(mP16v, mP8v, mV16v, mV8v,
                                        out, nullptr, nullptr, RS,
                                        SS, DD, (size_t)SS * DD, SS, 0, SS, 1.0f);
}

// round 9
// speedup vs baseline: 1.5200x; 1.5200x over previous
#include <cuda_runtime.h>
#include <cuda.h>
#include <cuda_bf16.h>
#include <cstdint>

// Shapes (fixed): B=4, S=2048, D=1024
#define BB 4
#define SS 2048
#define DD 1024
#define MQKV (BB * SS)            // 8192

// ---- GEMM tile: 128x128 block, BK=32 (64B rows, SW64), 4 warps, 3 stages,
// ---- 2 CTAs per SM for cross-CTA latency hiding.
#define TM_ 128
#define TN_ 128
#define BK 32
#define A_TILE_B (128 * 64)       // 8192
#define B_TILE_B (128 * 64)       // 8192
#define STAGE_B  (2 * A_TILE_B + 2 * B_TILE_B)   // 32768
#define NSTAGE 3
#define SMEM_TOTAL (1024 + NSTAGE * STAGE_B)     // 99328  (x2 CTAs = 198656)
#define NT 128                    // 4 warps

// ---------------- scratch (device globals; allocation-free rule) -----------
__device__ __align__(256) __nv_bfloat16 g_xh[(size_t)MQKV * DD];
__device__ __align__(256) __nv_bfloat16 g_xl[(size_t)MQKV * DD];
__device__ __align__(256) __nv_bfloat16 g_Wth[3][(size_t)DD * DD];   // W^T hi (Q,K,V)
__device__ __align__(256) __nv_bfloat16 g_Wtl[3][(size_t)DD * DD];   // W^T lo
__device__ __align__(256) float         g_F[(size_t)MQKV * DD];      // fp32 staging (V)
__device__ __align__(256) __nv_bfloat16 g_QKh[2][(size_t)MQKV * DD]; // Q,K hi planes
__device__ __align__(256) __nv_bfloat16 g_QKl[2][(size_t)MQKV * DD]; // Q,K lo planes
__device__ __align__(256) __nv_bfloat16 g_Vth[(size_t)DD * MQKV];    // V^T [D, B*S]
__device__ __align__(256) __nv_bfloat16 g_Vtl[(size_t)DD * MQKV];
__device__ __align__(256) __nv_bfloat16 g_Ph[(size_t)BB * SS * SS];  // exp(S) hi
__device__ __align__(256) __nv_bfloat16 g_Pl[(size_t)BB * SS * SS];  // exp(S) lo
__device__ __align__(256) float         g_RS[MQKV];                  // row sums

// ---------------- PTX helpers ----------------------------------------------
__device__ __forceinline__ uint32_t smem_u32(const void* p) {
    uint32_t a;
    asm("{ .reg .u64 t; cvta.to.shared.u64 t, %1; cvt.u32.u64 %0, t; }"
        : "=r"(a) : "l"(p));
    return a;
}
#define LDSM4(r, addr)                                                      \
    asm volatile("ldmatrix.sync.aligned.m8n8.x4.shared.b16 {%0,%1,%2,%3}, [%4];" \
        : "=r"((r)[0]), "=r"((r)[1]), "=r"((r)[2]), "=r"((r)[3]) : "r"(addr))

#define MMA(c, a, b0, b1)                                                   \
    asm volatile("mma.sync.aligned.m16n8k16.row.col.f32.bf16.bf16.f32 "     \
        "{%0,%1,%2,%3}, {%4,%5,%6,%7}, {%8,%9}, {%0,%1,%2,%3};"             \
        : "+f"((c)[0]), "+f"((c)[1]), "+f"((c)[2]), "+f"((c)[3])            \
        : "r"((a)[0]), "r"((a)[1]), "r"((a)[2]), "r"((a)[3]),               \
          "r"(b0), "r"(b1))

__device__ __forceinline__ void tma2d(uint32_t dst, const void* map,
                                      int x, int y, uint32_t mb) {
    asm volatile(
        "cp.async.bulk.tensor.2d.shared::cta.global.tile.mbarrier::complete_tx::bytes "
        "[%0], [%1, {%2, %3}], [%4];"
        :: "r"(dst), "l"(map), "r"(x), "r"(y), "r"(mb) : "memory");
}
#define MB_INIT(mb, c) \
    asm volatile("mbarrier.init.shared.b64 [%0], %1;" :: "r"(mb), "r"(c) : "memory")
#define MB_EXPECT(mb, bytes) \
    asm volatile("mbarrier.arrive.expect_tx.shared.b64 _, [%0], %1;" \
                 :: "r"(mb), "r"(bytes) : "memory")
#define MB_WAIT(mb, ph) do {                                               \
    asm volatile("{\n\t.reg .pred P;\n\t"                                  \
        "WL%=:\n\t"                                                        \
        "mbarrier.try_wait.parity.acquire.cta.shared::cta.b64 P, [%0], %1;\n\t" \
        "@!P bra WL%=;\n\t}"                                               \
        :: "r"(mb), "r"(ph) : "memory");                                   \
} while (0)

// ---------------------------------------------------------------------------
// Split-bf16 HMMA GEMM, TMA pipeline (3 stages, SW64, BK=32), 2 CTAs/SM.
//   acc[M,N] = (Ah+Al)[M,K] @ (Bh+Bl)[N,K]^T   (3-term split, fp32 acc)
// EPI=1 (projections, z in {0,1,2}):
//        z<2 : split-bf16 write to Chi/Clo + z*strideC
//        z==2: fp32 write to C (staging for V)
// EPI=2 (scores): p = expf(acc*alpha); split-bf16 write to Chi/Clo + z*strideC
// EPI=3 (AV):     o = acc / RS[z*SS + row]; fp32 write to C + z*strideC
// Grid (N/128, M/128, z). 128 threads, 4 warps of 64x64.
// ---------------------------------------------------------------------------
template <int EPI>
__global__ __launch_bounds__(NT, 2)
void mma_gemm(const __grid_constant__ CUtensorMap mAh,
              const __grid_constant__ CUtensorMap mAl,
              const __grid_constant__ CUtensorMap mBh,
              const __grid_constant__ CUtensorMap mBl,
              float* __restrict__ C,
              __nv_bfloat16* __restrict__ Chi, __nv_bfloat16* __restrict__ Clo,
              const float* __restrict__ RS,
              int K, int ldc, size_t strideC,
              int zRowA, int zRowB, int zColB, float alpha)
{
    extern __shared__ char smem[];
    const uint32_t sbase = smem_u32(smem);
    const uint32_t bufs  = (sbase + 1023u) & ~1023u;   // 1024-align
    const uint32_t mbar  = sbase;                      // 3 mbarriers
    const int tid  = threadIdx.x;
    const int lane = tid & 31, wid = tid >> 5;
    const int bz = blockIdx.z;
    const int tileM = blockIdx.y * TM_;
    const int tileN = blockIdx.x * TN_;
    const int rowA0 = tileM + bz * zRowA;
    const int rowB0 = tileN + bz * zRowB;
    const int colB0 = bz * zColB;

    if (tid == 0) {
        #pragma unroll
        for (int i = 0; i < NSTAGE; i++) MB_INIT(mbar + 8 * i, 1);
    }
    __syncthreads();

    const int nst = K / BK;
    auto issue = [&](int slot, int s) {
        const uint32_t buf = bufs + (uint32_t)slot * STAGE_B;
        const uint32_t mb  = mbar + (uint32_t)slot * 8;
        const int kt = s * BK;
        MB_EXPECT(mb, STAGE_B);
        tma2d(buf,                           &mAh, kt,         rowA0, mb);
        tma2d(buf + A_TILE_B,                &mAl, kt,         rowA0, mb);
        tma2d(buf + 2 * A_TILE_B,            &mBh, kt + colB0, rowB0, mb);
        tma2d(buf + 2 * A_TILE_B + B_TILE_B, &mBl, kt + colB0, rowB0, mb);
    };
    if (tid == 0) { issue(0, 0); issue(1, 1); }

    const int wm = (wid >> 1) * 64;        // warp M offset (0/64)
    const int wn = (wid & 1) * 64;         // warp N offset (0/64)

    // ldmatrix lane addressing; SW64: xor = ((row>>1)&3)<<4 on byte column
    uint32_t aoff[4], axor[4], boff[4], bxor[4];
    {
        const int arl = wm + (lane & 15);
        const int brl = wn + (lane & 7) + ((lane >> 4) * 8);
        #pragma unroll
        for (int i = 0; i < 4; i++) {
            int ar = arl + i * 16;
            aoff[i] = (uint32_t)(ar * 64);
            axor[i] = (uint32_t)(((ar >> 1) & 3) << 4);
            int br = brl + i * 16;
            boff[i] = (uint32_t)(br * 64);
            bxor[i] = (uint32_t)(((br >> 1) & 3) << 4);
        }
    }
    const uint32_t a_colb = (uint32_t)((lane >> 4) * 16);
    const uint32_t b_colb = (uint32_t)(((lane >> 3) & 1) * 16);

    float acc[4][8][4];
    #pragma unroll
    for (int i = 0; i < 4; i++)
        #pragma unroll
        for (int j = 0; j < 8; j++)
            #pragma unroll
            for (int r = 0; r < 4; r++) acc[i][j][r] = 0.0f;

    int st = 0, ph = 0;                    // wait cursor
    int ibuf = 2;                          // next issue slot
    for (int s = 0; s < nst; s++) {
        const uint32_t buf = bufs + (uint32_t)st * STAGE_B;
        MB_WAIT(mbar + (uint32_t)st * 8, (uint32_t)ph);
        if (tid == 0 && s + 2 < nst) issue(ibuf, s + 2);
        if (++ibuf == NSTAGE) ibuf = 0;

        const uint32_t bufA = buf;
        const uint32_t bufB = buf + 2 * A_TILE_B;
        #pragma unroll
        for (int ks = 0; ks < 2; ks++) {
            const uint32_t kb = (uint32_t)(ks * 32);
            uint32_t ah[4][4], al[4][4], bh[4][4], bl[4][4];
            #pragma unroll
            for (int mt = 0; mt < 4; mt++) {
                uint32_t ra = bufA + aoff[mt] + ((kb + a_colb) ^ axor[mt]);
                LDSM4(ah[mt], ra);
                LDSM4(al[mt], ra + A_TILE_B);
            }
            #pragma unroll
            for (int j = 0; j < 4; j++) {
                uint32_t rb = bufB + boff[j] + ((kb + b_colb) ^ bxor[j]);
                LDSM4(bh[j], rb);
                LDSM4(bl[j], rb + B_TILE_B);
            }
            #pragma unroll
            for (int mt = 0; mt < 4; mt++) {
                #pragma unroll
                for (int j = 0; j < 4; j++) {
                    MMA(acc[mt][2 * j],     ah[mt], bh[j][0], bh[j][1]);
                    MMA(acc[mt][2 * j + 1], ah[mt], bh[j][2], bh[j][3]);
                    MMA(acc[mt][2 * j],     ah[mt], bl[j][0], bl[j][1]);
                    MMA(acc[mt][2 * j + 1], ah[mt], bl[j][2], bl[j][3]);
                    MMA(acc[mt][2 * j],     al[mt], bh[j][0], bh[j][1]);
                    MMA(acc[mt][2 * j + 1], al[mt], bh[j][2], bh[j][3]);
                }
            }
        }
        __syncthreads();
        if (++st == NSTAGE) { st = 0; ph ^= 1; }
    }

    // ---- epilogue ----
    const int er = lane >> 2;              // 0..7
    const int ec = (lane & 3) * 2;         // 0,2,4,6
    const bool fp32_path = (EPI == 3) || (EPI == 1 && bz == 2);
    float* Cz = C;
    if (EPI == 3) Cz = C + (size_t)bz * strideC;
    __nv_bfloat16* ChiZ = Chi;  __nv_bfloat16* CloZ = Clo;
    if (EPI == 1 || EPI == 2) {
        ChiZ = Chi + (size_t)bz * strideC;
        CloZ = Clo + (size_t)bz * strideC;
    }
    const float* rs = (EPI == 3) ? (RS + (size_t)bz * SS) : nullptr;

    #pragma unroll
    for (int mt = 0; mt < 4; mt++) {
        const int rloc = tileM + wm + mt * 16 + er;
        float inv0 = 0.f, inv1 = 0.f;
        if (EPI == 3) { inv0 = 1.0f / rs[rloc]; inv1 = 1.0f / rs[rloc + 8]; }
        #pragma unroll
        for (int j = 0; j < 8; j++) {
            const int col = tileN + wn + j * 8 + ec;
            float v0 = acc[mt][j][0] * alpha, v1 = acc[mt][j][1] * alpha;
            float v2 = acc[mt][j][2] * alpha, v3 = acc[mt][j][3] * alpha;
            if (EPI == 2) {
                v0 = __expf(v0); v1 = __expf(v1);
                v2 = __expf(v2); v3 = __expf(v3);
            }
            if (EPI == 3) { v0 *= inv0; v1 *= inv0; v2 *= inv1; v3 *= inv1; }
            if (fp32_path) {
                *reinterpret_cast<float2*>(&Cz[(size_t)rloc * ldc + col]) =
                    make_float2(v0, v1);
                *reinterpret_cast<float2*>(&Cz[(size_t)(rloc + 8) * ldc + col]) =
                    make_float2(v2, v3);
            } else {
                __nv_bfloat162 h0, l0, h1, l1;
                h0.x = __float2bfloat16(v0);  h0.y = __float2bfloat16(v1);
                l0.x = __float2bfloat16(v0 - __bfloat162float(h0.x));
                l0.y = __float2bfloat16(v1 - __bfloat162float(h0.y));
                h1.x = __float2bfloat16(v2);  h1.y = __float2bfloat16(v3);
                l1.x = __float2bfloat16(v2 - __bfloat162float(h1.x));
                l1.y = __float2bfloat16(v3 - __bfloat162float(h1.y));
                size_t o0 = (size_t)rloc * ldc + col;
                size_t o1 = (size_t)(rloc + 8) * ldc + col;
                *reinterpret_cast<__nv_bfloat162*>(&ChiZ[o0]) = h0;
                *reinterpret_cast<__nv_bfloat162*>(&CloZ[o0]) = l0;
                *reinterpret_cast<__nv_bfloat162*>(&ChiZ[o1]) = h1;
                *reinterpret_cast<__nv_bfloat162*>(&CloZ[o1]) = l1;
            }
        }
    }
}

// ---------------------------------------------------------------------------
// fp32 -> (hi, lo) bf16 split, elementwise
// ---------------------------------------------------------------------------
__global__ __launch_bounds__(256)
void split_kernel(const float* __restrict__ in,
                  __nv_bfloat16* __restrict__ hi, __nv_bfloat16* __restrict__ lo,
                  size_t n4)
{
    size_t i = (size_t)blockIdx.x * blockDim.x + threadIdx.x;
    if (i >= n4) return;
    float4 v = reinterpret_cast<const float4*>(in)[i];
    __nv_bfloat16 h0 = __float2bfloat16(v.x), h1 = __float2bfloat16(v.y);
    __nv_bfloat16 h2 = __float2bfloat16(v.z), h3 = __float2bfloat16(v.w);
    __nv_bfloat162 hA; hA.x = h0; hA.y = h1;
    __nv_bfloat162 hB; hB.x = h2; hB.y = h3;
    __nv_bfloat162 lA, lB;
    lA.x = __float2bfloat16(v.x - __bfloat162float(h0));
    lA.y = __float2bfloat16(v.y - __bfloat162float(h1));
    lB.x = __float2bfloat16(v.z - __bfloat162float(h2));
    lB.y = __float2bfloat16(v.w - __bfloat162float(h3));
    reinterpret_cast<__nv_bfloat162*>(hi)[2 * i]     = hA;
    reinterpret_cast<__nv_bfloat162*>(hi)[2 * i + 1] = hB;
    reinterpret_cast<__nv_bfloat162*>(lo)[2 * i]     = lA;
    reinterpret_cast<__nv_bfloat162*>(lo)[2 * i + 1] = lB;
}

// ---------------------------------------------------------------------------
// fp32 [R,C] -> transposed (hi, lo) bf16 [C,R]
// ---------------------------------------------------------------------------
__global__ __launch_bounds__(256)
void tsplit_kernel(const float* __restrict__ in,
                   __nv_bfloat16* __restrict__ hi, __nv_bfloat16* __restrict__ lo,
                   int R, int C)
{
    __shared__ float tile[32][33];
    const int c0 = blockIdx.x * 32, r0 = blockIdx.y * 32;
    const int tx = threadIdx.x, ty = threadIdx.y;   // 32 x 8
    #pragma unroll
    for (int j = 0; j < 32; j += 8)
        tile[ty + j][tx] = in[(size_t)(r0 + ty + j) * C + c0 + tx];
    __syncthreads();
    #pragma unroll
    for (int j = 0; j < 32; j += 8) {
        float v = tile[tx][ty + j];
        __nv_bfloat16 h = __float2bfloat16(v);
        size_t o = (size_t)(c0 + ty + j) * R + r0 + tx;
        hi[o] = h;
        lo[o] = __float2bfloat16(v - __bfloat162float(h));
    }
}

// ---------------------------------------------------------------------------
// Row sums of exp(S): RS[row] = sum_j (Ph[row][j] + Pl[row][j])
// ---------------------------------------------------------------------------
__global__ __launch_bounds__(256)
void rowsum_kernel(const __nv_bfloat16* __restrict__ Ph,
                   const __nv_bfloat16* __restrict__ Pl,
                   float* __restrict__ RS)
{
    __shared__ float sh[8];
    const size_t base = (size_t)blockIdx.x * SS;
    const int tid = threadIdx.x;
    const __nv_bfloat162* ph = reinterpret_cast<const __nv_bfloat162*>(Ph + base);
    const __nv_bfloat162* pl = reinterpret_cast<const __nv_bfloat162*>(Pl + base);
    float s = 0.0f;
    #pragma unroll
    for (int i = 0; i < 4; i++) {
        __nv_bfloat162 a = ph[tid + i * 256];
        __nv_bfloat162 b = pl[tid + i * 256];
        s += __bfloat162float(a.x) + __bfloat162float(a.y)
           + __bfloat162float(b.x) + __bfloat162float(b.y);
    }
    #pragma unroll
    for (int o = 16; o > 0; o >>= 1) s += __shfl_xor_sync(~0u, s, o);
    if ((tid & 31) == 0) sh[tid >> 5] = s;
    __syncthreads();
    if (tid < 32) {
        s = (tid < 8) ? sh[tid] : 0.0f;
        #pragma unroll
        for (int o = 4; o > 0; o >>= 1) s += __shfl_xor_sync(~0u, s, o);
        if (tid == 0) RS[blockIdx.x] = s;
    }
}

// ---------------------------------------------------------------------------
// Host: tensor-map builder (driver entry point, no -lcuda needed)
// ---------------------------------------------------------------------------
typedef CUresult (*PFN_TMAPENC)(CUtensorMap*, CUtensorMapDataType, cuuint32_t,
                                void*, const cuuint64_t*, const cuuint64_t*,
                                const cuuint32_t*, const cuuint32_t*,
                                CUtensorMapInterleave, CUtensorMapSwizzle,
                                CUtensorMapL2promotion, CUtensorMapFloatOOBfill);

static void make_map(PFN_TMAPENC enc, CUtensorMap* m, void* base,
                     unsigned long long cols, unsigned long long rows)
{
    cuuint64_t dims[2]    = {cols, rows};
    cuuint64_t strides[1] = {cols * 2};
    cuuint32_t box[2]     = {32, 128};          // 32 bf16 = 64B rows, 128 rows
    cuuint32_t es[2]      = {1, 1};
    enc(m, CU_TENSOR_MAP_DATA_TYPE_BFLOAT16, 2, base, dims, strides, box, es,
        CU_TENSOR_MAP_INTERLEAVE_NONE, CU_TENSOR_MAP_SWIZZLE_64B,
        CU_TENSOR_MAP_L2_PROMOTION_L2_128B, CU_TENSOR_MAP_FLOAT_OOB_FILL_NONE);
}

extern "C" void kernel_launch(void* const* d_in, const int* in_sizes, int n_in,
                              void* d_out, int out_size)
{
    const float* x  = (const float*)d_in[0];
    const float* WQ = (const float*)d_in[1];
    const float* WK = (const float*)d_in[2];
    const float* WV = (const float*)d_in[3];
    float* out = (float*)d_out;

    __nv_bfloat16 *xh, *xl, *Wth, *Wtl, *QKh, *QKl, *Vth, *Vtl, *Ph, *Pl;
    float *F, *RS;
    cudaGetSymbolAddress((void**)&xh,  g_xh);
    cudaGetSymbolAddress((void**)&xl,  g_xl);
    cudaGetSymbolAddress((void**)&Wth, g_Wth);
    cudaGetSymbolAddress((void**)&Wtl, g_Wtl);
    cudaGetSymbolAddress((void**)&F,   g_F);
    cudaGetSymbolAddress((void**)&QKh, g_QKh);
    cudaGetSymbolAddress((void**)&QKl, g_QKl);
    cudaGetSymbolAddress((void**)&Vth, g_Vth);
    cudaGetSymbolAddress((void**)&Vtl, g_Vtl);
    cudaGetSymbolAddress((void**)&Ph,  g_Ph);
    cudaGetSymbolAddress((void**)&Pl,  g_Pl);
    cudaGetSymbolAddress((void**)&RS,  g_RS);

    const size_t nQK = (size_t)MQKV * DD;       // plane stride for Q/K
    __nv_bfloat16* Qh = QKh;            __nv_bfloat16* Ql = QKl;
    __nv_bfloat16* Kh = QKh + nQK;      __nv_bfloat16* Kl = QKl + nQK;

    PFN_TMAPENC enc = nullptr;
    cudaDriverEntryPointQueryResult qres;
    cudaGetDriverEntryPoint("cuTensorMapEncodeTiled", (void**)&enc,
                            cudaEnableDefault, &qres);

    const size_t nW = (size_t)DD * DD;
    CUtensorMap mXh, mXl, mWh, mWl, mQh, mQl, mKh, mKl, mPh, mPl, mVh, mVl;
    make_map(enc, &mXh, xh, DD, MQKV);
    make_map(enc, &mXl, xl, DD, MQKV);
    make_map(enc, &mWh, Wth, DD, 3 * DD);       // all 3 weight planes, z-row offset
    make_map(enc, &mWl, Wtl, DD, 3 * DD);
    make_map(enc, &mQh, Qh, DD, MQKV);
    make_map(enc, &mQl, Ql, DD, MQKV);
    make_map(enc, &mKh, Kh, DD, MQKV);
    make_map(enc, &mKl, Kl, DD, MQKV);
    make_map(enc, &mPh, Ph, SS, MQKV);
    make_map(enc, &mPl, Pl, SS, MQKV);
    make_map(enc, &mVh, Vth, MQKV, DD);
    make_map(enc, &mVl, Vtl, MQKV, DD);

    cudaFuncSetAttribute(mma_gemm<1>, cudaFuncAttributeMaxDynamicSharedMemorySize, SMEM_TOTAL);
    cudaFuncSetAttribute(mma_gemm<2>, cudaFuncAttributeMaxDynamicSharedMemorySize, SMEM_TOTAL);
    cudaFuncSetAttribute(mma_gemm<3>, cudaFuncAttributeMaxDynamicSharedMemorySize, SMEM_TOTAL);

    const size_t n4x = (size_t)MQKV * DD / 4;
    dim3 tb(32, 8);

    // 1) input conversions
    split_kernel<<<(unsigned)((n4x + 255) / 256), 256>>>(x, xh, xl, n4x);
    tsplit_kernel<<<dim3(DD / 32, DD / 32), tb>>>(WQ, Wth + 0 * nW, Wtl + 0 * nW, DD, DD);
    tsplit_kernel<<<dim3(DD / 32, DD / 32), tb>>>(WK, Wth + 1 * nW, Wtl + 1 * nW, DD, DD);
    tsplit_kernel<<<dim3(DD / 32, DD / 32), tb>>>(WV, Wth + 2 * nW, Wtl + 2 * nW, DD, DD);

    // 2) all 3 projections in one launch (z: 0=Q split, 1=K split, 2=V fp32)
    dim3 gp(DD / TN_, MQKV / TM_, 3);                 // 8 x 64 x 3
    mma_gemm<1><<<gp, NT, SMEM_TOTAL>>>(mXh, mXl, mWh, mWl,
                                        F, QKh, QKl, nullptr,
                                        DD, DD, nQK, 0, DD, 0, 1.0f);
    tsplit_kernel<<<dim3(DD / 32, MQKV / 32), tb>>>(F, Vth, Vtl, MQKV, DD);

    // 3) scores + exp fused: P = exp(Q @ K^T / 32), split-bf16 out
    dim3 gs(SS / TN_, SS / TM_, BB);                  // 16 x 16 x 4
    mma_gemm<2><<<gs, NT, SMEM_TOTAL>>>(mQh, mQl, mKh, mKl,
                                        nullptr, Ph, Pl, nullptr,
                                        DD, SS, (size_t)SS * SS, SS, SS, 0,
                                        1.0f / 32.0f);

    // 4) row sums of exp(S)
    rowsum_kernel<<<MQKV, 256>>>(Ph, Pl, RS);

    // 5) O = (P @ V^T-rows) / rowsum
    dim3 go(DD / TN_, SS / TM_, BB);                  // 8 x 16 x 4
    mma_gemm<3><<<go, NT, SMEM_TOTAL>>>(mPh, mPl, mVh, mVl,
                                        out, nullptr, nullptr, RS,
                                        SS, DD, (size_t)SS * DD, SS, 0, SS, 1.0f);
}

// round 11
// speedup vs baseline: 2.1407x; 1.4084x over previous
#include <cuda_runtime.h>
#include <cuda.h>
#include <cuda_fp16.h>
#include <cstdint>

// Shapes (fixed): B=4, S=2048, D=1024
#define BB 4
#define SS 2048
#define DD 1024
#define MQKV (BB * SS)            // 8192

// ---- GEMM tile: 128x128, BK=32 (64B rows, SW64), 4 warps, 4 stages,
// ---- 2 CTAs/SM. Stage = A(fp16) + Bh + Bl = 3 tiles.
#define TM_ 128
#define TN_ 128
#define BK 32
#define A_TILE_B (128 * 64)       // 8192
#define B_TILE_B (128 * 64)       // 8192
#define STAGE_B  (A_TILE_B + 2 * B_TILE_B)       // 24576
#define NSTAGE 4
#define SMEM_TOTAL (1024 + NSTAGE * STAGE_B)     // 99328 (x2 CTAs = 198656)
#define NT 128                    // 4 warps

// ---------------- scratch (device globals; allocation-free rule) -----------
__device__ __align__(256) __half g_x16[(size_t)MQKV * DD];           // A for proj
__device__ __align__(256) __half g_Wh[(size_t)3 * DD * DD];          // W^T hi planes
__device__ __align__(256) __half g_Wl[(size_t)3 * DD * DD];          // W^T lo planes
__device__ __align__(256) float  g_F[(size_t)MQKV * DD];             // fp32 staging (V)
__device__ __align__(256) __half g_Q16[(size_t)MQKV * DD];           // Q (A-role)
__device__ __align__(256) __half g_Kh[(size_t)MQKV * DD];            // K hi (B-role)
__device__ __align__(256) __half g_Kl[(size_t)MQKV * DD];            // K lo
__device__ __align__(256) __half g_Vh[(size_t)DD * MQKV];            // V^T hi (B-role)
__device__ __align__(256) __half g_Vl[(size_t)DD * MQKV];            // V^T lo
__device__ __align__(256) __half g_P16[(size_t)BB * SS * SS];        // exp(S) (A-role)
__device__ __align__(256) float  g_RS[MQKV];                         // row sums

// ---------------- PTX helpers ----------------------------------------------
__device__ __forceinline__ uint32_t smem_u32(const void* p) {
    uint32_t a;
    asm("{ .reg .u64 t; cvta.to.shared.u64 t, %1; cvt.u32.u64 %0, t; }"
        : "=r"(a) : "l"(p));
    return a;
}
#define LDSM4(r, addr)                                                      \
    asm volatile("ldmatrix.sync.aligned.m8n8.x4.shared.b16 {%0,%1,%2,%3}, [%4];" \
        : "=r"((r)[0]), "=r"((r)[1]), "=r"((r)[2]), "=r"((r)[3]) : "r"(addr))

#define MMA(c, a, b0, b1)                                                   \
    asm volatile("mma.sync.aligned.m16n8k16.row.col.f32.f16.f16.f32 "       \
        "{%0,%1,%2,%3}, {%4,%5,%6,%7}, {%8,%9}, {%0,%1,%2,%3};"             \
        : "+f"((c)[0]), "+f"((c)[1]), "+f"((c)[2]), "+f"((c)[3])            \
        : "r"((a)[0]), "r"((a)[1]), "r"((a)[2]), "r"((a)[3]),               \
          "r"(b0), "r"(b1))

__device__ __forceinline__ void tma2d(uint32_t dst, const void* map,
                                      int x, int y, uint32_t mb) {
    asm volatile(
        "cp.async.bulk.tensor.2d.shared::cta.global.tile.mbarrier::complete_tx::bytes "
        "[%0], [%1, {%2, %3}], [%4];"
        :: "r"(dst), "l"(map), "r"(x), "r"(y), "r"(mb) : "memory");
}
#define MB_INIT(mb, c) \
    asm volatile("mbarrier.init.shared.b64 [%0], %1;" :: "r"(mb), "r"(c) : "memory")
#define MB_EXPECT(mb, bytes) \
    asm volatile("mbarrier.arrive.expect_tx.shared.b64 _, [%0], %1;" \
                 :: "r"(mb), "r"(bytes) : "memory")
#define MB_WAIT(mb, ph) do {                                               \
    asm volatile("{\n\t.reg .pred P;\n\t"                                  \
        "WL%=:\n\t"                                                        \
        "mbarrier.try_wait.parity.acquire.cta.shared::cta.b64 P, [%0], %1;\n\t" \
        "@!P bra WL%=;\n\t}"                                               \
        :: "r"(mb), "r"(ph) : "memory");                                   \
} while (0)

// ---------------------------------------------------------------------------
// Asymmetric fp16 GEMM:  acc[M,N] = A[M,K](fp16) @ (Bh+Bl)[N,K]^T, fp32 acc.
// 2 MMAs per k16. TMA pipeline (4 stages, SW64), 2 CTAs/SM.
// EPI=1 (projections, z in {0,1,2}): z0 -> fp16 O16 (Q, A-role)
//                                    z1 -> fp16 split Ohi/Olo (K, B-role)
//                                    z2 -> fp32 C (V staging)
// EPI=2 (scores): p = expf(acc*alpha) -> fp16 O16 + z*strideC (P, A-role)
// EPI=3 (AV):     o = acc / RS[z*SS+row] -> fp32 C + z*strideC
// Grid (N/128, M/128, z). 128 threads, 4 warps of 64x64.
// ---------------------------------------------------------------------------
template <int EPI>
__global__ __launch_bounds__(NT, 2)
void mma_gemm(const __grid_constant__ CUtensorMap mA,
              const __grid_constant__ CUtensorMap mBh,
              const __grid_constant__ CUtensorMap mBl,
              float* __restrict__ C,
              __half* __restrict__ O16,
              __half* __restrict__ Ohi, __half* __restrict__ Olo,
              const float* __restrict__ RS,
              int K, int ldc, size_t strideC,
              int zRowA, int zRowB, int zColB, float alpha)
{
    extern __shared__ char smem[];
    const uint32_t sbase = smem_u32(smem);
    const uint32_t bufs  = (sbase + 1023u) & ~1023u;   // 1024-align
    const uint32_t mbar  = sbase;                      // 4 mbarriers
    const int tid  = threadIdx.x;
    const int lane = tid & 31, wid = tid >> 5;
    const int bz = blockIdx.z;
    const int tileM = blockIdx.y * TM_;
    const int tileN = blockIdx.x * TN_;
    const int rowA0 = tileM + bz * zRowA;
    const int rowB0 = tileN + bz * zRowB;
    const int colB0 = bz * zColB;

    if (tid == 0) {
        #pragma unroll
        for (int i = 0; i < NSTAGE; i++) MB_INIT(mbar + 8 * i, 1);
    }
    __syncthreads();

    const int nst = K / BK;
    auto issue = [&](int s) {
        const uint32_t buf = bufs + (uint32_t)(s & (NSTAGE - 1)) * STAGE_B;
        const uint32_t mb  = mbar + (uint32_t)(s & (NSTAGE - 1)) * 8;
        const int kt = s * BK;
        MB_EXPECT(mb, STAGE_B);
        tma2d(buf,                      &mA,  kt,         rowA0, mb);
        tma2d(buf + A_TILE_B,           &mBh, kt + colB0, rowB0, mb);
        tma2d(buf + A_TILE_B + B_TILE_B, &mBl, kt + colB0, rowB0, mb);
    };
    if (tid == 0) { issue(0); issue(1); issue(2); }

    const int wm = (wid >> 1) * 64;        // warp M offset (0/64)
    const int wn = (wid & 1) * 64;         // warp N offset (0/64)

    // ldmatrix lane addressing; SW64: xor = ((row>>1)&3)<<4 on byte column
    uint32_t aoff[4], axor[4], boff[4], bxor[4];
    {
        const int arl = wm + (lane & 15);
        const int brl = wn + (lane & 7) + ((lane >> 4) * 8);
        #pragma unroll
        for (int i = 0; i < 4; i++) {
            int ar = arl + i * 16;
            aoff[i] = (uint32_t)(ar * 64);
            axor[i] = (uint32_t)(((ar >> 1) & 3) << 4);
            int br = brl + i * 16;
            boff[i] = (uint32_t)(br * 64);
            bxor[i] = (uint32_t)(((br >> 1) & 3) << 4);
        }
    }
    const uint32_t a_colb = (uint32_t)((lane >> 4) * 16);
    const uint32_t b_colb = (uint32_t)(((lane >> 3) & 1) * 16);

    float acc[4][8][4];
    #pragma unroll
    for (int i = 0; i < 4; i++)
        #pragma unroll
        for (int j = 0; j < 8; j++)
            #pragma unroll
            for (int r = 0; r < 4; r++) acc[i][j][r] = 0.0f;

    for (int s = 0; s < nst; s++) {
        const uint32_t buf = bufs + (uint32_t)(s & (NSTAGE - 1)) * STAGE_B;
        MB_WAIT(mbar + (uint32_t)(s & (NSTAGE - 1)) * 8, (uint32_t)((s >> 2) & 1));
        if (tid == 0 && s + 3 < nst) issue(s + 3);   // keep 3 stages in flight

        const uint32_t bufA = buf;
        const uint32_t bufB = buf + A_TILE_B;
        #pragma unroll
        for (int ks = 0; ks < 2; ks++) {
            const uint32_t kb = (uint32_t)(ks * 32);
            uint32_t a[4][4], bh[4][4], bl[4][4];
            #pragma unroll
            for (int mt = 0; mt < 4; mt++)
                LDSM4(a[mt], bufA + aoff[mt] + ((kb + a_colb) ^ axor[mt]));
            #pragma unroll
            for (int j = 0; j < 4; j++) {
                uint32_t rb = bufB + boff[j] + ((kb + b_colb) ^ bxor[j]);
                LDSM4(bh[j], rb);
                LDSM4(bl[j], rb + B_TILE_B);
            }
            #pragma unroll
            for (int mt = 0; mt < 4; mt++) {
                #pragma unroll
                for (int j = 0; j < 4; j++) {
                    MMA(acc[mt][2 * j],     a[mt], bh[j][0], bh[j][1]);
                    MMA(acc[mt][2 * j + 1], a[mt], bh[j][2], bh[j][3]);
                    MMA(acc[mt][2 * j],     a[mt], bl[j][0], bl[j][1]);
                    MMA(acc[mt][2 * j + 1], a[mt], bl[j][2], bl[j][3]);
                }
            }
        }
        __syncthreads();
    }

    // ---- epilogue ----
    const int er = lane >> 2;              // 0..7
    const int ec = (lane & 3) * 2;         // 0,2,4,6
    const bool fp32_path = (EPI == 3) || (EPI == 1 && bz == 2);
    const bool split_path = (EPI == 1 && bz == 1);
    float* Cz = (EPI == 3) ? C + (size_t)bz * strideC : C;
    __half* O16z = (EPI == 2) ? O16 + (size_t)bz * strideC : O16;
    const float* rs = (EPI == 3) ? (RS + (size_t)bz * SS) : nullptr;

    #pragma unroll
    for (int mt = 0; mt < 4; mt++) {
        const int rloc = tileM + wm + mt * 16 + er;
        float inv0 = 0.f, inv1 = 0.f;
        if (EPI == 3) { inv0 = 1.0f / rs[rloc]; inv1 = 1.0f / rs[rloc + 8]; }
        #pragma unroll
        for (int j = 0; j < 8; j++) {
            const int col = tileN + wn + j * 8 + ec;
            float v0 = acc[mt][j][0] * alpha, v1 = acc[mt][j][1] * alpha;
            float v2 = acc[mt][j][2] * alpha, v3 = acc[mt][j][3] * alpha;
            if (EPI == 2) {
                v0 = __expf(v0); v1 = __expf(v1);
                v2 = __expf(v2); v3 = __expf(v3);
            }
            if (EPI == 3) { v0 *= inv0; v1 *= inv0; v2 *= inv1; v3 *= inv1; }
            const size_t o0 = (size_t)rloc * ldc + col;
            const size_t o1 = (size_t)(rloc + 8) * ldc + col;
            if (fp32_path) {
                *reinterpret_cast<float2*>(&Cz[o0]) = make_float2(v0, v1);
                *reinterpret_cast<float2*>(&Cz[o1]) = make_float2(v2, v3);
            } else if (split_path) {
                __half2 h0 = __floats2half2_rn(v0, v1);
                __half2 h1 = __floats2half2_rn(v2, v3);
                __half2 l0 = __floats2half2_rn(v0 - __low2float(h0),
                                               v1 - __high2float(h0));
                __half2 l1 = __floats2half2_rn(v2 - __low2float(h1),
                                               v3 - __high2float(h1));
                *reinterpret_cast<__half2*>(&Ohi[o0]) = h0;
                *reinterpret_cast<__half2*>(&Olo[o0]) = l0;
                *reinterpret_cast<__half2*>(&Ohi[o1]) = h1;
                *reinterpret_cast<__half2*>(&Olo[o1]) = l1;
            } else {
                *reinterpret_cast<__half2*>(&O16z[o0]) = __floats2half2_rn(v0, v1);
                *reinterpret_cast<__half2*>(&O16z[o1]) = __floats2half2_rn(v2, v3);
            }
        }
    }
}

// ---------------------------------------------------------------------------
// fp32 -> fp16 cast, elementwise (A-role input x)
// ---------------------------------------------------------------------------
__global__ __launch_bounds__(256)
void castA_kernel(const float* __restrict__ in, __half* __restrict__ o16,
                  size_t n4)
{
    size_t i = (size_t)blockIdx.x * blockDim.x + threadIdx.x;
    if (i >= n4) return;
    float4 v = reinterpret_cast<const float4*>(in)[i];
    reinterpret_cast<__half2*>(o16)[2 * i]     = __floats2half2_rn(v.x, v.y);
    reinterpret_cast<__half2*>(o16)[2 * i + 1] = __floats2half2_rn(v.z, v.w);
}

// ---------------------------------------------------------------------------
// fp32 [R,C] -> transposed fp16 (hi, lo) [C,R]  (B-role producers)
// ---------------------------------------------------------------------------
__global__ __launch_bounds__(256)
void tsplit_kernel(const float* __restrict__ in,
                   __half* __restrict__ hi, __half* __restrict__ lo,
                   int R, int C)
{
    __shared__ float tile[32][33];
    const int c0 = blockIdx.x * 32, r0 = blockIdx.y * 32;
    const int tx = threadIdx.x, ty = threadIdx.y;   // 32 x 8
    #pragma unroll
    for (int j = 0; j < 32; j += 8)
        tile[ty + j][tx] = in[(size_t)(r0 + ty + j) * C + c0 + tx];
    __syncthreads();
    #pragma unroll
    for (int j = 0; j < 32; j += 8) {
        float v = tile[tx][ty + j];
        __half h = __float2half_rn(v);
        size_t o = (size_t)(c0 + ty + j) * R + r0 + tx;
        hi[o] = h;
        lo[o] = __float2half_rn(v - __half2float(h));
    }
}

// ---------------------------------------------------------------------------
// Row sums of exp(S) from fp16 P
// ---------------------------------------------------------------------------
__global__ __launch_bounds__(256)
void rowsum_kernel(const __half* __restrict__ P16, float* __restrict__ RS)
{
    __shared__ float sh[8];
    const size_t base = (size_t)blockIdx.x * SS;
    const int tid = threadIdx.x;
    const __half2* ph = reinterpret_cast<const __half2*>(P16 + base);
    float s = 0.0f;
    #pragma unroll
    for (int i = 0; i < 4; i++) {
        float2 a = __half22float2(ph[tid + i * 256]);
        s += a.x + a.y;
    }
    #pragma unroll
    for (int o = 16; o > 0; o >>= 1) s += __shfl_xor_sync(~0u, s, o);
    if ((tid & 31) == 0) sh[tid >> 5] = s;
    __syncthreads();
    if (tid < 32) {
        s = (tid < 8) ? sh[tid] : 0.0f;
        #pragma unroll
        for (int o = 4; o > 0; o >>= 1) s += __shfl_xor_sync(~0u, s, o);
        if (tid == 0) RS[blockIdx.x] = s;
    }
}

// ---------------------------------------------------------------------------
// Host: tensor-map builder (driver entry point, no -lcuda needed)
// ---------------------------------------------------------------------------
typedef CUresult (*PFN_TMAPENC)(CUtensorMap*, CUtensorMapDataType, cuuint32_t,
                                void*, const cuuint64_t*, const cuuint64_t*,
                                const cuuint32_t*, const cuuint32_t*,
                                CUtensorMapInterleave, CUtensorMapSwizzle,
                                CUtensorMapL2promotion, CUtensorMapFloatOOBfill);

static void make_map(PFN_TMAPENC enc, CUtensorMap* m, void* base,
                     unsigned long long cols, unsigned long long rows)
{
    cuuint64_t dims[2]    = {cols, rows};
    cuuint64_t strides[1] = {cols * 2};
    cuuint32_t box[2]     = {32, 128};          // 32 fp16 = 64B rows, 128 rows
    cuuint32_t es[2]      = {1, 1};
    enc(m, CU_TENSOR_MAP_DATA_TYPE_FLOAT16, 2, base, dims, strides, box, es,
        CU_TENSOR_MAP_INTERLEAVE_NONE, CU_TENSOR_MAP_SWIZZLE_64B,
        CU_TENSOR_MAP_L2_PROMOTION_L2_128B, CU_TENSOR_MAP_FLOAT_OOB_FILL_NONE);
}

extern "C" void kernel_launch(void* const* d_in, const int* in_sizes, int n_in,
                              void* d_out, int out_size)
{
    const float* x  = (const float*)d_in[0];
    const float* WQ = (const float*)d_in[1];
    const float* WK = (const float*)d_in[2];
    const float* WV = (const float*)d_in[3];
    float* out = (float*)d_out;

    __half *x16, *Wh, *Wl, *Q16, *Kh, *Kl, *Vh, *Vl, *P16;
    float *F, *RS;
    cudaGetSymbolAddress((void**)&x16, g_x16);
    cudaGetSymbolAddress((void**)&Wh,  g_Wh);
    cudaGetSymbolAddress((void**)&Wl,  g_Wl);
    cudaGetSymbolAddress((void**)&F,   g_F);
    cudaGetSymbolAddress((void**)&Q16, g_Q16);
    cudaGetSymbolAddress((void**)&Kh,  g_Kh);
    cudaGetSymbolAddress((void**)&Kl,  g_Kl);
    cudaGetSymbolAddress((void**)&Vh,  g_Vh);
    cudaGetSymbolAddress((void**)&Vl,  g_Vl);
    cudaGetSymbolAddress((void**)&P16, g_P16);
    cudaGetSymbolAddress((void**)&RS,  g_RS);

    PFN_TMAPENC enc = nullptr;
    cudaDriverEntryPointQueryResult qres;
    cudaGetDriverEntryPoint("cuTensorMapEncodeTiled", (void**)&enc,
                            cudaEnableDefault, &qres);

    const size_t nW = (size_t)DD * DD;
    CUtensorMap mX, mWhv, mWlv, mQ, mKhv, mKlv, mP, mVhv, mVlv;
    make_map(enc, &mX,  x16, DD, MQKV);
    make_map(enc, &mWhv, Wh, DD, 3 * DD);       // 3 weight planes, z-row offset
    make_map(enc, &mWlv, Wl, DD, 3 * DD);
    make_map(enc, &mQ,  Q16, DD, MQKV);
    make_map(enc, &mKhv, Kh, DD, MQKV);
    make_map(enc, &mKlv, Kl, DD, MQKV);
    make_map(enc, &mP,  P16, SS, MQKV);
    make_map(enc, &mVhv, Vh, MQKV, DD);
    make_map(enc, &mVlv, Vl, MQKV, DD);

    cudaFuncSetAttribute(mma_gemm<1>, cudaFuncAttributeMaxDynamicSharedMemorySize, SMEM_TOTAL);
    cudaFuncSetAttribute(mma_gemm<2>, cudaFuncAttributeMaxDynamicSharedMemorySize, SMEM_TOTAL);
    cudaFuncSetAttribute(mma_gemm<3>, cudaFuncAttributeMaxDynamicSharedMemorySize, SMEM_TOTAL);

    const size_t n4x = (size_t)MQKV * DD / 4;
    dim3 tb(32, 8);

    // 1) input conversions
    castA_kernel<<<(unsigned)((n4x + 255) / 256), 256>>>(x, x16, n4x);
    tsplit_kernel<<<dim3(DD / 32, DD / 32), tb>>>(WQ, Wh + 0 * nW, Wl + 0 * nW, DD, DD);
    tsplit_kernel<<<dim3(DD / 32, DD / 32), tb>>>(WK, Wh + 1 * nW, Wl + 1 * nW, DD, DD);
    tsplit_kernel<<<dim3(DD / 32, DD / 32), tb>>>(WV, Wh + 2 * nW, Wl + 2 * nW, DD, DD);

    // 2) all 3 projections in one launch (z: 0=Q fp16, 1=K split, 2=V fp32)
    dim3 gp(DD / TN_, MQKV / TM_, 3);                 // 8 x 64 x 3
    mma_gemm<1><<<gp, NT, SMEM_TOTAL>>>(mX, mWhv, mWlv,
                                        F, Q16, Kh, Kl, nullptr,
                                        DD, DD, 0, 0, DD, 0, 1.0f);
    tsplit_kernel<<<dim3(DD / 32, MQKV / 32), tb>>>(F, Vh, Vl, MQKV, DD);

    // 3) scores + exp fused: P = exp(Q @ K^T / 32) -> fp16
    dim3 gs(SS / TN_, SS / TM_, BB);                  // 16 x 16 x 4
    mma_gemm<2><<<gs, NT, SMEM_TOTAL>>>(mQ, mKhv, mKlv,
                                        nullptr, P16, nullptr, nullptr, nullptr,
                                        DD, SS, (size_t)SS * SS, SS, SS, 0,
                                        1.0f / 32.0f);

    // 4) row sums of exp(S)
    rowsum_kernel<<<MQKV, 256>>>(P16, RS);

    // 5) O = (P @ V^T-rows) / rowsum
    dim3 go(DD / TN_, SS / TM_, BB);                  // 8 x 16 x 4
    mma_gemm<3><<<go, NT, SMEM_TOTAL>>>(mP, mVhv, mVlv,
                                        out, nullptr, nullptr, nullptr, RS,
                                        SS, DD, (size_t)SS * DD, SS, 0, SS, 1.0f);
}

// round 13
// speedup vs baseline: 3.8137x; 1.7815x over previous
#include <cuda_runtime.h>
#include <cuda.h>
#include <cuda_fp16.h>
#include <cstdint>

// Shapes (fixed): B=4, S=2048, D=1024
#define BB 4
#define SS 2048
#define DD 1024
#define MQKV (BB * SS)            // 8192

// ---- GEMM tile: 128x128, BK=32 (64B rows, SW64), 4 warps, 4 stages,
// ---- 2 CTAs/SM. Stage = A + B = 2 fp16 tiles (16 KB).
#define TM_ 128
#define TN_ 128
#define BK 32
#define A_TILE_B (128 * 64)       // 8192
#define B_TILE_B (128 * 64)       // 8192
#define STAGE_B  (A_TILE_B + B_TILE_B)           // 16384
#define NSTAGE 4
#define SMEM_TOTAL (1024 + NSTAGE * STAGE_B)     // 66560 (x2 CTAs = 133120)
#define NT 128                    // 4 warps

// ---------------- scratch (device globals; allocation-free rule) -----------
__device__ __align__(256) __half g_x16[(size_t)MQKV * DD];           // x fp16
__device__ __align__(256) __half g_Wt[(size_t)3 * DD * DD];          // W^T planes
__device__ __align__(256) float  g_F[(size_t)MQKV * DD];             // fp32 staging (V)
__device__ __align__(256) __half g_QK16[(size_t)2 * MQKV * DD];      // Q,K planes
__device__ __align__(256) __half g_Vt[(size_t)DD * MQKV];            // V^T fp16
__device__ __align__(256) __half g_P16[(size_t)BB * SS * SS];        // exp(S) fp16
__device__ __align__(256) float  g_RS[MQKV];                         // row sums

// ---------------- PTX helpers ----------------------------------------------
__device__ __forceinline__ uint32_t smem_u32(const void* p) {
    uint32_t a;
    asm("{ .reg .u64 t; cvta.to.shared.u64 t, %1; cvt.u32.u64 %0, t; }"
        : "=r"(a) : "l"(p));
    return a;
}
#define LDSM4(r, addr)                                                      \
    asm volatile("ldmatrix.sync.aligned.m8n8.x4.shared.b16 {%0,%1,%2,%3}, [%4];" \
        : "=r"((r)[0]), "=r"((r)[1]), "=r"((r)[2]), "=r"((r)[3]) : "r"(addr))

#define MMA(c, a, b0, b1)                                                   \
    asm volatile("mma.sync.aligned.m16n8k16.row.col.f32.f16.f16.f32 "       \
        "{%0,%1,%2,%3}, {%4,%5,%6,%7}, {%8,%9}, {%0,%1,%2,%3};"             \
        : "+f"((c)[0]), "+f"((c)[1]), "+f"((c)[2]), "+f"((c)[3])            \
        : "r"((a)[0]), "r"((a)[1]), "r"((a)[2]), "r"((a)[3]),               \
          "r"(b0), "r"(b1))

__device__ __forceinline__ void tma2d(uint32_t dst, const void* map,
                                      int x, int y, uint32_t mb) {
    asm volatile(
        "cp.async.bulk.tensor.2d.shared::cta.global.tile.mbarrier::complete_tx::bytes "
        "[%0], [%1, {%2, %3}], [%4];"
        :: "r"(dst), "l"(map), "r"(x), "r"(y), "r"(mb) : "memory");
}
#define MB_INIT(mb, c) \
    asm volatile("mbarrier.init.shared.b64 [%0], %1;" :: "r"(mb), "r"(c) : "memory")
#define MB_EXPECT(mb, bytes) \
    asm volatile("mbarrier.arrive.expect_tx.shared.b64 _, [%0], %1;" \
                 :: "r"(mb), "r"(bytes) : "memory")
#define MB_WAIT(mb, ph) do {                                               \
    asm volatile("{\n\t.reg .pred P;\n\t"                                  \
        "WL%=:\n\t"                                                        \
        "mbarrier.try_wait.parity.acquire.cta.shared::cta.b64 P, [%0], %1;\n\t" \
        "@!P bra WL%=;\n\t}"                                               \
        :: "r"(mb), "r"(ph) : "memory");                                   \
} while (0)

// ---------------------------------------------------------------------------
// Pure fp16 GEMM (fp32 acc):  acc[M,N] = A[M,K] @ B[N,K]^T.
// 1 MMA per k16. TMA pipeline (4 stages, SW64), 2 CTAs/SM.
// EPI=1 (projections, z in {0,1,2}): z<2 -> fp16 O16 + z*strideC (Q,K planes)
//                                    z==2 -> fp32 C (V staging)
// EPI=2 (scores): p = expf(acc*alpha) -> fp16 O16 + z*strideC
// EPI=3 (AV):     o = acc / RS[z*SS+row] -> fp32 C + z*strideC
// Grid (N/128, M/128, z). 128 threads, 4 warps of 64x64.
// ---------------------------------------------------------------------------
template <int EPI>
__global__ __launch_bounds__(NT, 2)
void mma_gemm(const __grid_constant__ CUtensorMap mA,
              const __grid_constant__ CUtensorMap mB,
              float* __restrict__ C,
              __half* __restrict__ O16,
              const float* __restrict__ RS,
              int K, int ldc, size_t strideC,
              int zRowA, int zRowB, int zColB, float alpha)
{
    extern __shared__ char smem[];
    const uint32_t sbase = smem_u32(smem);
    const uint32_t bufs  = (sbase + 1023u) & ~1023u;   // 1024-align
    const uint32_t mbar  = sbase;                      // 4 mbarriers
    const int tid  = threadIdx.x;
    const int lane = tid & 31, wid = tid >> 5;
    const int bz = blockIdx.z;
    const int tileM = blockIdx.y * TM_;
    const int tileN = blockIdx.x * TN_;
    const int rowA0 = tileM + bz * zRowA;
    const int rowB0 = tileN + bz * zRowB;
    const int colB0 = bz * zColB;

    if (tid == 0) {
        #pragma unroll
        for (int i = 0; i < NSTAGE; i++) MB_INIT(mbar + 8 * i, 1);
    }
    __syncthreads();

    const int nst = K / BK;
    auto issue = [&](int s) {
        const uint32_t buf = bufs + (uint32_t)(s & (NSTAGE - 1)) * STAGE_B;
        const uint32_t mb  = mbar + (uint32_t)(s & (NSTAGE - 1)) * 8;
        const int kt = s * BK;
        MB_EXPECT(mb, STAGE_B);
        tma2d(buf,            &mA, kt,         rowA0, mb);
        tma2d(buf + A_TILE_B, &mB, kt + colB0, rowB0, mb);
    };
    if (tid == 0) { issue(0); issue(1); issue(2); }

    const int wm = (wid >> 1) * 64;        // warp M offset (0/64)
    const int wn = (wid & 1) * 64;         // warp N offset (0/64)

    // ldmatrix lane addressing; SW64: xor = ((row>>1)&3)<<4 on byte column
    uint32_t aoff[4], axor[4], boff[4], bxor[4];
    {
        const int arl = wm + (lane & 15);
        const int brl = wn + (lane & 7) + ((lane >> 4) * 8);
        #pragma unroll
        for (int i = 0; i < 4; i++) {
            int ar = arl + i * 16;
            aoff[i] = (uint32_t)(ar * 64);
            axor[i] = (uint32_t)(((ar >> 1) & 3) << 4);
            int br = brl + i * 16;
            boff[i] = (uint32_t)(br * 64);
            bxor[i] = (uint32_t)(((br >> 1) & 3) << 4);
        }
    }
    const uint32_t a_colb = (uint32_t)((lane >> 4) * 16);
    const uint32_t b_colb = (uint32_t)(((lane >> 3) & 1) * 16);

    float acc[4][8][4];
    #pragma unroll
    for (int i = 0; i < 4; i++)
        #pragma unroll
        for (int j = 0; j < 8; j++)
            #pragma unroll
            for (int r = 0; r < 4; r++) acc[i][j][r] = 0.0f;

    for (int s = 0; s < nst; s++) {
        const uint32_t buf = bufs + (uint32_t)(s & (NSTAGE - 1)) * STAGE_B;
        MB_WAIT(mbar + (uint32_t)(s & (NSTAGE - 1)) * 8, (uint32_t)((s >> 2) & 1));
        if (tid == 0 && s + 3 < nst) issue(s + 3);   // keep 3 stages in flight

        const uint32_t bufA = buf;
        const uint32_t bufB = buf + A_TILE_B;
        #pragma unroll
        for (int ks = 0; ks < 2; ks++) {
            const uint32_t kb = (uint32_t)(ks * 32);
            uint32_t a[4][4], b[4][4];
            #pragma unroll
            for (int mt = 0; mt < 4; mt++)
                LDSM4(a[mt], bufA + aoff[mt] + ((kb + a_colb) ^ axor[mt]));
            #pragma unroll
            for (int j = 0; j < 4; j++)
                LDSM4(b[j], bufB + boff[j] + ((kb + b_colb) ^ bxor[j]));
            #pragma unroll
            for (int mt = 0; mt < 4; mt++) {
                #pragma unroll
                for (int j = 0; j < 4; j++) {
                    MMA(acc[mt][2 * j],     a[mt], b[j][0], b[j][1]);
                    MMA(acc[mt][2 * j + 1], a[mt], b[j][2], b[j][3]);
                }
            }
        }
        __syncthreads();
    }

    // ---- epilogue ----
    const int er = lane >> 2;              // 0..7
    const int ec = (lane & 3) * 2;         // 0,2,4,6
    const bool fp32_path = (EPI == 3) || (EPI == 1 && bz == 2);
    float* Cz = (EPI == 3) ? C + (size_t)bz * strideC : C;
    __half* O16z = O16 + (size_t)bz * strideC;
    const float* rs = (EPI == 3) ? (RS + (size_t)bz * SS) : nullptr;

    #pragma unroll
    for (int mt = 0; mt < 4; mt++) {
        const int rloc = tileM + wm + mt * 16 + er;
        float inv0 = 0.f, inv1 = 0.f;
        if (EPI == 3) { inv0 = 1.0f / rs[rloc]; inv1 = 1.0f / rs[rloc + 8]; }
        #pragma unroll
        for (int j = 0; j < 8; j++) {
            const int col = tileN + wn + j * 8 + ec;
            float v0 = acc[mt][j][0] * alpha, v1 = acc[mt][j][1] * alpha;
            float v2 = acc[mt][j][2] * alpha, v3 = acc[mt][j][3] * alpha;
            if (EPI == 2) {
                v0 = __expf(v0); v1 = __expf(v1);
                v2 = __expf(v2); v3 = __expf(v3);
            }
            if (EPI == 3) { v0 *= inv0; v1 *= inv0; v2 *= inv1; v3 *= inv1; }
            const size_t o0 = (size_t)rloc * ldc + col;
            const size_t o1 = (size_t)(rloc + 8) * ldc + col;
            if (fp32_path) {
                *reinterpret_cast<float2*>(&Cz[o0]) = make_float2(v0, v1);
                *reinterpret_cast<float2*>(&Cz[o1]) = make_float2(v2, v3);
            } else {
                *reinterpret_cast<__half2*>(&O16z[o0]) = __floats2half2_rn(v0, v1);
                *reinterpret_cast<__half2*>(&O16z[o1]) = __floats2half2_rn(v2, v3);
            }
        }
    }
}

// ---------------------------------------------------------------------------
// fp32 -> fp16 cast, elementwise
// ---------------------------------------------------------------------------
__global__ __launch_bounds__(256)
void cast_kernel(const float* __restrict__ in, __half* __restrict__ o16,
                 size_t n4)
{
    size_t i = (size_t)blockIdx.x * blockDim.x + threadIdx.x;
    if (i >= n4) return;
    float4 v = reinterpret_cast<const float4*>(in)[i];
    reinterpret_cast<__half2*>(o16)[2 * i]     = __floats2half2_rn(v.x, v.y);
    reinterpret_cast<__half2*>(o16)[2 * i + 1] = __floats2half2_rn(v.z, v.w);
}

// ---------------------------------------------------------------------------
// fp32 [R,C] -> transposed fp16 [C,R]
// ---------------------------------------------------------------------------
__global__ __launch_bounds__(256)
void tcast_kernel(const float* __restrict__ in, __half* __restrict__ o16,
                  int R, int C)
{
    __shared__ float tile[32][33];
    const int c0 = blockIdx.x * 32, r0 = blockIdx.y * 32;
    const int tx = threadIdx.x, ty = threadIdx.y;   // 32 x 8
    #pragma unroll
    for (int j = 0; j < 32; j += 8)
        tile[ty + j][tx] = in[(size_t)(r0 + ty + j) * C + c0 + tx];
    __syncthreads();
    #pragma unroll
    for (int j = 0; j < 32; j += 8) {
        float v = tile[tx][ty + j];
        o16[(size_t)(c0 + ty + j) * R + r0 + tx] = __float2half_rn(v);
    }
}

// ---------------------------------------------------------------------------
// Row sums of exp(S) from fp16 P
// ---------------------------------------------------------------------------
__global__ __launch_bounds__(256)
void rowsum_kernel(const __half* __restrict__ P16, float* __restrict__ RS)
{
    __shared__ float sh[8];
    const size_t base = (size_t)blockIdx.x * SS;
    const int tid = threadIdx.x;
    const __half2* ph = reinterpret_cast<const __half2*>(P16 + base);
    float s = 0.0f;
    #pragma unroll
    for (int i = 0; i < 4; i++) {
        float2 a = __half22float2(ph[tid + i * 256]);
        s += a.x + a.y;
    }
    #pragma unroll
    for (int o = 16; o > 0; o >>= 1) s += __shfl_xor_sync(~0u, s, o);
    if ((tid & 31) == 0) sh[tid >> 5] = s;
    __syncthreads();
    if (tid < 32) {
        s = (tid < 8) ? sh[tid] : 0.0f;
        #pragma unroll
        for (int o = 4; o > 0; o >>= 1) s += __shfl_xor_sync(~0u, s, o);
        if (tid == 0) RS[blockIdx.x] = s;
    }
}

// ---------------------------------------------------------------------------
// Host: tensor-map builder (driver entry point, no -lcuda needed)
// ---------------------------------------------------------------------------
typedef CUresult (*PFN_TMAPENC)(CUtensorMap*, CUtensorMapDataType, cuuint32_t,
                                void*, const cuuint64_t*, const cuuint64_t*,
                                const cuuint32_t*, const cuuint32_t*,
                                CUtensorMapInterleave, CUtensorMapSwizzle,
                                CUtensorMapL2promotion, CUtensorMapFloatOOBfill);

static void make_map(PFN_TMAPENC enc, CUtensorMap* m, void* base,
                     unsigned long long cols, unsigned long long rows)
{
    cuuint64_t dims[2]    = {cols, rows};
    cuuint64_t strides[1] = {cols * 2};
    cuuint32_t box[2]     = {32, 128};          // 32 fp16 = 64B rows, 128 rows
    cuuint32_t es[2]      = {1, 1};
    enc(m, CU_TENSOR_MAP_DATA_TYPE_FLOAT16, 2, base, dims, strides, box, es,
        CU_TENSOR_MAP_INTERLEAVE_NONE, CU_TENSOR_MAP_SWIZZLE_64B,
        CU_TENSOR_MAP_L2_PROMOTION_L2_128B, CU_TENSOR_MAP_FLOAT_OOB_FILL_NONE);
}

extern "C" void kernel_launch(void* const* d_in, const int* in_sizes, int n_in,
                              void* d_out, int out_size)
{
    const float* x  = (const float*)d_in[0];
    const float* WQ = (const float*)d_in[1];
    const float* WK = (const float*)d_in[2];
    const float* WV = (const float*)d_in[3];
    float* out = (float*)d_out;

    __half *x16, *Wt, *QK16, *Vt, *P16;
    float *F, *RS;
    cudaGetSymbolAddress((void**)&x16, g_x16);
    cudaGetSymbolAddress((void**)&Wt,  g_Wt);
    cudaGetSymbolAddress((void**)&F,   g_F);
    cudaGetSymbolAddress((void**)&QK16, g_QK16);
    cudaGetSymbolAddress((void**)&Vt,  g_Vt);
    cudaGetSymbolAddress((void**)&P16, g_P16);
    cudaGetSymbolAddress((void**)&RS,  g_RS);

    const size_t nQK = (size_t)MQKV * DD;       // Q/K plane stride
    const size_t nW  = (size_t)DD * DD;

    PFN_TMAPENC enc = nullptr;
    cudaDriverEntryPointQueryResult qres;
    cudaGetDriverEntryPoint("cuTensorMapEncodeTiled", (void**)&enc,
                            cudaEnableDefault, &qres);

    CUtensorMap mX, mW, mQ, mK, mP, mV;
    make_map(enc, &mX, x16, DD, MQKV);
    make_map(enc, &mW, Wt, DD, 3 * DD);         // 3 weight planes, z-row offset
    make_map(enc, &mQ, QK16, DD, MQKV);
    make_map(enc, &mK, QK16 + nQK, DD, MQKV);
    make_map(enc, &mP, P16, SS, MQKV);
    make_map(enc, &mV, Vt, MQKV, DD);

    cudaFuncSetAttribute(mma_gemm<1>, cudaFuncAttributeMaxDynamicSharedMemorySize, SMEM_TOTAL);
    cudaFuncSetAttribute(mma_gemm<2>, cudaFuncAttributeMaxDynamicSharedMemorySize, SMEM_TOTAL);
    cudaFuncSetAttribute(mma_gemm<3>, cudaFuncAttributeMaxDynamicSharedMemorySize, SMEM_TOTAL);

    const size_t n4x = (size_t)MQKV * DD / 4;
    dim3 tb(32, 8);

    // 1) input conversions
    cast_kernel<<<(unsigned)((n4x + 255) / 256), 256>>>(x, x16, n4x);
    tcast_kernel<<<dim3(DD / 32, DD / 32), tb>>>(WQ, Wt + 0 * nW, DD, DD);
    tcast_kernel<<<dim3(DD / 32, DD / 32), tb>>>(WK, Wt + 1 * nW, DD, DD);
    tcast_kernel<<<dim3(DD / 32, DD / 32), tb>>>(WV, Wt + 2 * nW, DD, DD);

    // 2) all 3 projections in one launch (z: 0=Q fp16, 1=K fp16, 2=V fp32)
    dim3 gp(DD / TN_, MQKV / TM_, 3);                 // 8 x 64 x 3
    mma_gemm<1><<<gp, NT, SMEM_TOTAL>>>(mX, mW,
                                        F, QK16, nullptr,
                                        DD, DD, nQK, 0, DD, 0, 1.0f);
    tcast_kernel<<<dim3(DD / 32, MQKV / 32), tb>>>(F, Vt, MQKV, DD);

    // 3) scores + exp fused: P = exp(Q @ K^T / 32) -> fp16
    dim3 gs(SS / TN_, SS / TM_, BB);                  // 16 x 16 x 4
    mma_gemm<2><<<gs, NT, SMEM_TOTAL>>>(mQ, mK,
                                        nullptr, P16, nullptr,
                                        DD, SS, (size_t)SS * SS, SS, SS, 0,
                                        1.0f / 32.0f);

    // 4) row sums of exp(S)
    rowsum_kernel<<<MQKV, 256>>>(P16, RS);

    // 5) O = (P @ V^T-rows) / rowsum
    dim3 go(DD / TN_, SS / TM_, BB);                  // 8 x 16 x 4
    mma_gemm<3><<<go, NT, SMEM_TOTAL>>>(mP, mV,
                                        out, nullptr, RS,
                                        SS, DD, (size_t)SS * DD, SS, 0, SS, 1.0f);
}

// round 14
// speedup vs baseline: 3.9426x; 1.0338x over previous
#include <cuda_runtime.h>
#include <cuda.h>
#include <cuda_fp16.h>
#include <cstdint>

// Shapes (fixed): B=4, S=2048, D=1024
#define BB 4
#define SS 2048
#define DD 1024
#define MQKV (BB * SS)            // 8192

// ---- GEMM tile: 128x128, BK=64 (128B rows, SW128), 4 warps, 3 stages,
// ---- 2 CTAs/SM. Stage = A + B = 2 fp16 tiles (32 KB).
#define TM_ 128
#define TN_ 128
#define BK 64
#define A_TILE_B (128 * 128)      // 16384
#define B_TILE_B (128 * 128)      // 16384
#define STAGE_B  (A_TILE_B + B_TILE_B)           // 32768
#define NSTAGE 3
#define SMEM_TOTAL (1024 + NSTAGE * STAGE_B)     // 99328 (x2 CTAs = 198656)
#define NT 128                    // 4 warps

// ---------------- scratch (device globals; allocation-free rule) -----------
__device__ __align__(256) __half g_x16[(size_t)MQKV * DD];           // x fp16
__device__ __align__(256) __half g_Wt[(size_t)3 * DD * DD];          // W^T planes
__device__ __align__(256) float  g_F[(size_t)MQKV * DD];             // fp32 staging (V)
__device__ __align__(256) __half g_QK16[(size_t)2 * MQKV * DD];      // Q,K planes
__device__ __align__(256) __half g_Vt[(size_t)DD * MQKV];            // V^T fp16
__device__ __align__(256) __half g_P16[(size_t)BB * SS * SS];        // exp(S) fp16
__device__ __align__(256) float  g_RS[MQKV];                         // row sums

// ---------------- PTX helpers ----------------------------------------------
__device__ __forceinline__ uint32_t smem_u32(const void* p) {
    uint32_t a;
    asm("{ .reg .u64 t; cvta.to.shared.u64 t, %1; cvt.u32.u64 %0, t; }"
        : "=r"(a) : "l"(p));
    return a;
}
#define LDSM4(r, addr)                                                      \
    asm volatile("ldmatrix.sync.aligned.m8n8.x4.shared.b16 {%0,%1,%2,%3}, [%4];" \
        : "=r"((r)[0]), "=r"((r)[1]), "=r"((r)[2]), "=r"((r)[3]) : "r"(addr))

#define MMA(c, a, b0, b1)                                                   \
    asm volatile("mma.sync.aligned.m16n8k16.row.col.f32.f16.f16.f32 "       \
        "{%0,%1,%2,%3}, {%4,%5,%6,%7}, {%8,%9}, {%0,%1,%2,%3};"             \
        : "+f"((c)[0]), "+f"((c)[1]), "+f"((c)[2]), "+f"((c)[3])            \
        : "r"((a)[0]), "r"((a)[1]), "r"((a)[2]), "r"((a)[3]),               \
          "r"(b0), "r"(b1))

__device__ __forceinline__ void tma2d(uint32_t dst, const void* map,
                                      int x, int y, uint32_t mb) {
    asm volatile(
        "cp.async.bulk.tensor.2d.shared::cta.global.tile.mbarrier::complete_tx::bytes "
        "[%0], [%1, {%2, %3}], [%4];"
        :: "r"(dst), "l"(map), "r"(x), "r"(y), "r"(mb) : "memory");
}
#define MB_INIT(mb, c) \
    asm volatile("mbarrier.init.shared.b64 [%0], %1;" :: "r"(mb), "r"(c) : "memory")
#define MB_EXPECT(mb, bytes) \
    asm volatile("mbarrier.arrive.expect_tx.shared.b64 _, [%0], %1;" \
                 :: "r"(mb), "r"(bytes) : "memory")
#define MB_WAIT(mb, ph) do {                                               \
    asm volatile("{\n\t.reg .pred P;\n\t"                                  \
        "WL%=:\n\t"                                                        \
        "mbarrier.try_wait.parity.acquire.cta.shared::cta.b64 P, [%0], %1;\n\t" \
        "@!P bra WL%=;\n\t}"                                               \
        :: "r"(mb), "r"(ph) : "memory");                                   \
} while (0)

// ---------------------------------------------------------------------------
// Pure fp16 GEMM (fp32 acc):  acc[M,N] = A[M,K] @ B[N,K]^T.
// 1 MMA per k16. TMA pipeline (3 stages, BK=64, SW128), 2 CTAs/SM.
// EPI=1 (projections, z in {0,1,2}): z<2 -> fp16 O16 + z*strideC (Q,K planes)
//                                    z==2 -> fp32 C (V staging)
// EPI=2 (scores): p = expf(acc*alpha) -> fp16 O16 + z*strideC,
//                 row sums atomically accumulated into RS[z*SS + row]
// EPI=3 (AV):     o = acc / RS[z*SS+row] -> fp32 C + z*strideC
// Grid (N/128, M/128, z). 128 threads, 4 warps of 64x64.
// ---------------------------------------------------------------------------
template <int EPI>
__global__ __launch_bounds__(NT, 2)
void mma_gemm(const __grid_constant__ CUtensorMap mA,
              const __grid_constant__ CUtensorMap mB,
              float* __restrict__ C,
              __half* __restrict__ O16,
              float* __restrict__ RS,
              int K, int ldc, size_t strideC,
              int zRowA, int zRowB, int zColB, float alpha)
{
    extern __shared__ char smem[];
    const uint32_t sbase = smem_u32(smem);
    const uint32_t bufs  = (sbase + 1023u) & ~1023u;   // 1024-align
    const uint32_t mbar  = sbase;                      // 3 mbarriers
    const int tid  = threadIdx.x;
    const int lane = tid & 31, wid = tid >> 5;
    const int bz = blockIdx.z;
    const int tileM = blockIdx.y * TM_;
    const int tileN = blockIdx.x * TN_;
    const int rowA0 = tileM + bz * zRowA;
    const int rowB0 = tileN + bz * zRowB;
    const int colB0 = bz * zColB;

    if (tid == 0) {
        #pragma unroll
        for (int i = 0; i < NSTAGE; i++) MB_INIT(mbar + 8 * i, 1);
    }
    __syncthreads();

    const int nst = K / BK;
    auto issue = [&](int slot, int s) {
        const uint32_t buf = bufs + (uint32_t)slot * STAGE_B;
        const uint32_t mb  = mbar + (uint32_t)slot * 8;
        const int kt = s * BK;
        MB_EXPECT(mb, STAGE_B);
        tma2d(buf,            &mA, kt,         rowA0, mb);
        tma2d(buf + A_TILE_B, &mB, kt + colB0, rowB0, mb);
    };
    if (tid == 0) { issue(0, 0); issue(1, 1); }

    const int wm = (wid >> 1) * 64;        // warp M offset (0/64)
    const int wn = (wid & 1) * 64;         // warp N offset (0/64)

    // ldmatrix lane addressing; SW128: xor = (row&7)<<4 on byte column
    uint32_t aoff[4], axor[4], boff[4], bxor[4];
    {
        const int arl = wm + (lane & 15);
        const int brl = wn + (lane & 7) + ((lane >> 4) * 8);
        #pragma unroll
        for (int i = 0; i < 4; i++) {
            int ar = arl + i * 16;
            aoff[i] = (uint32_t)(ar * 128);
            axor[i] = (uint32_t)((ar & 7) << 4);
            int br = brl + i * 16;
            boff[i] = (uint32_t)(br * 128);
            bxor[i] = (uint32_t)((br & 7) << 4);
        }
    }
    const uint32_t a_colb = (uint32_t)((lane >> 4) * 16);
    const uint32_t b_colb = (uint32_t)(((lane >> 3) & 1) * 16);

    float acc[4][8][4];
    #pragma unroll
    for (int i = 0; i < 4; i++)
        #pragma unroll
        for (int j = 0; j < 8; j++)
            #pragma unroll
            for (int r = 0; r < 4; r++) acc[i][j][r] = 0.0f;

    int st = 0, ph = 0, ibuf = 2;
    for (int s = 0; s < nst; s++) {
        const uint32_t buf = bufs + (uint32_t)st * STAGE_B;
        MB_WAIT(mbar + (uint32_t)st * 8, (uint32_t)ph);
        if (tid == 0 && s + 2 < nst) issue(ibuf, s + 2);
        if (++ibuf == NSTAGE) ibuf = 0;

        const uint32_t bufA = buf;
        const uint32_t bufB = buf + A_TILE_B;
        #pragma unroll
        for (int ks = 0; ks < 4; ks++) {
            const uint32_t kb = (uint32_t)(ks * 32);
            uint32_t a[4][4], b[4][4];
            #pragma unroll
            for (int mt = 0; mt < 4; mt++)
                LDSM4(a[mt], bufA + aoff[mt] + ((kb + a_colb) ^ axor[mt]));
            #pragma unroll
            for (int j = 0; j < 4; j++)
                LDSM4(b[j], bufB + boff[j] + ((kb + b_colb) ^ bxor[j]));
            #pragma unroll
            for (int mt = 0; mt < 4; mt++) {
                #pragma unroll
                for (int j = 0; j < 4; j++) {
                    MMA(acc[mt][2 * j],     a[mt], b[j][0], b[j][1]);
                    MMA(acc[mt][2 * j + 1], a[mt], b[j][2], b[j][3]);
                }
            }
        }
        __syncthreads();
        if (++st == NSTAGE) { st = 0; ph ^= 1; }
    }

    // ---- epilogue ----
    const int er = lane >> 2;              // 0..7
    const int ec = (lane & 3) * 2;         // 0,2,4,6
    const bool fp32_path = (EPI == 3) || (EPI == 1 && bz == 2);
    float* Cz = (EPI == 3) ? C + (size_t)bz * strideC : C;
    __half* O16z = O16 + (size_t)bz * strideC;
    float* RSz = RS + (size_t)bz * SS;

    #pragma unroll
    for (int mt = 0; mt < 4; mt++) {
        const int rloc = tileM + wm + mt * 16 + er;
        float inv0 = 0.f, inv1 = 0.f;
        if (EPI == 3) { inv0 = 1.0f / RSz[rloc]; inv1 = 1.0f / RSz[rloc + 8]; }
        float rs0 = 0.f, rs1 = 0.f;
        #pragma unroll
        for (int j = 0; j < 8; j++) {
            const int col = tileN + wn + j * 8 + ec;
            float v0 = acc[mt][j][0] * alpha, v1 = acc[mt][j][1] * alpha;
            float v2 = acc[mt][j][2] * alpha, v3 = acc[mt][j][3] * alpha;
            if (EPI == 2) {
                v0 = __expf(v0); v1 = __expf(v1);
                v2 = __expf(v2); v3 = __expf(v3);
                rs0 += v0 + v1;  rs1 += v2 + v3;
            }
            if (EPI == 3) { v0 *= inv0; v1 *= inv0; v2 *= inv1; v3 *= inv1; }
            const size_t o0 = (size_t)rloc * ldc + col;
            const size_t o1 = (size_t)(rloc + 8) * ldc + col;
            if (fp32_path) {
                *reinterpret_cast<float2*>(&Cz[o0]) = make_float2(v0, v1);
                *reinterpret_cast<float2*>(&Cz[o1]) = make_float2(v2, v3);
            } else {
                *reinterpret_cast<__half2*>(&O16z[o0]) = __floats2half2_rn(v0, v1);
                *reinterpret_cast<__half2*>(&O16z[o1]) = __floats2half2_rn(v2, v3);
            }
        }
        if (EPI == 2) {
            // reduce across the 4 lanes of the quad (same row pair)
            rs0 += __shfl_xor_sync(~0u, rs0, 1);
            rs0 += __shfl_xor_sync(~0u, rs0, 2);
            rs1 += __shfl_xor_sync(~0u, rs1, 1);
            rs1 += __shfl_xor_sync(~0u, rs1, 2);
            if ((lane & 3) == 0) {
                atomicAdd(&RSz[rloc], rs0);
                atomicAdd(&RSz[rloc + 8], rs1);
            }
        }
    }
}

// ---------------------------------------------------------------------------
// fp32 -> fp16 cast, elementwise
// ---------------------------------------------------------------------------
__global__ __launch_bounds__(256)
void cast_kernel(const float* __restrict__ in, __half* __restrict__ o16,
                 size_t n4)
{
    size_t i = (size_t)blockIdx.x * blockDim.x + threadIdx.x;
    if (i >= n4) return;
    float4 v = reinterpret_cast<const float4*>(in)[i];
    reinterpret_cast<__half2*>(o16)[2 * i]     = __floats2half2_rn(v.x, v.y);
    reinterpret_cast<__half2*>(o16)[2 * i + 1] = __floats2half2_rn(v.z, v.w);
}

// ---------------------------------------------------------------------------
// fp32 [R,C] -> transposed fp16 [C,R]
// ---------------------------------------------------------------------------
__global__ __launch_bounds__(256)
void tcast_kernel(const float* __restrict__ in, __half* __restrict__ o16,
                  int R, int C)
{
    __shared__ float tile[32][33];
    const int c0 = blockIdx.x * 32, r0 = blockIdx.y * 32;
    const int tx = threadIdx.x, ty = threadIdx.y;   // 32 x 8
    #pragma unroll
    for (int j = 0; j < 32; j += 8)
        tile[ty + j][tx] = in[(size_t)(r0 + ty + j) * C + c0 + tx];
    __syncthreads();
    #pragma unroll
    for (int j = 0; j < 32; j += 8) {
        float v = tile[tx][ty + j];
        o16[(size_t)(c0 + ty + j) * R + r0 + tx] = __float2half_rn(v);
    }
}

// ---------------------------------------------------------------------------
// Host: tensor-map builder (driver entry point, no -lcuda needed)
// ---------------------------------------------------------------------------
typedef CUresult (*PFN_TMAPENC)(CUtensorMap*, CUtensorMapDataType, cuuint32_t,
                                void*, const cuuint64_t*, const cuuint64_t*,
                                const cuuint32_t*, const cuuint32_t*,
                                CUtensorMapInterleave, CUtensorMapSwizzle,
                                CUtensorMapL2promotion, CUtensorMapFloatOOBfill);

static void make_map(PFN_TMAPENC enc, CUtensorMap* m, void* base,
                     unsigned long long cols, unsigned long long rows)
{
    cuuint64_t dims[2]    = {cols, rows};
    cuuint64_t strides[1] = {cols * 2};
    cuuint32_t box[2]     = {64, 128};          // 64 fp16 = 128B rows, 128 rows
    cuuint32_t es[2]      = {1, 1};
    enc(m, CU_TENSOR_MAP_DATA_TYPE_FLOAT16, 2, base, dims, strides, box, es,
        CU_TENSOR_MAP_INTERLEAVE_NONE, CU_TENSOR_MAP_SWIZZLE_128B,
        CU_TENSOR_MAP_L2_PROMOTION_L2_128B, CU_TENSOR_MAP_FLOAT_OOB_FILL_NONE);
}

extern "C" void kernel_launch(void* const* d_in, const int* in_sizes, int n_in,
                              void* d_out, int out_size)
{
    const float* x  = (const float*)d_in[0];
    const float* WQ = (const float*)d_in[1];
    const float* WK = (const float*)d_in[2];
    const float* WV = (const float*)d_in[3];
    float* out = (float*)d_out;

    __half *x16, *Wt, *QK16, *Vt, *P16;
    float *F, *RS;
    cudaGetSymbolAddress((void**)&x16, g_x16);
    cudaGetSymbolAddress((void**)&Wt,  g_Wt);
    cudaGetSymbolAddress((void**)&F,   g_F);
    cudaGetSymbolAddress((void**)&QK16, g_QK16);
    cudaGetSymbolAddress((void**)&Vt,  g_Vt);
    cudaGetSymbolAddress((void**)&P16, g_P16);
    cudaGetSymbolAddress((void**)&RS,  g_RS);

    const size_t nQK = (size_t)MQKV * DD;       // Q/K plane stride
    const size_t nW  = (size_t)DD * DD;

    PFN_TMAPENC enc = nullptr;
    cudaDriverEntryPointQueryResult qres;
    cudaGetDriverEntryPoint("cuTensorMapEncodeTiled", (void**)&enc,
                            cudaEnableDefault, &qres);

    CUtensorMap mX, mW, mQ, mK, mP, mV;
    make_map(enc, &mX, x16, DD, MQKV);
    make_map(enc, &mW, Wt, DD, 3 * DD);         // 3 weight planes, z-row offset
    make_map(enc, &mQ, QK16, DD, MQKV);
    make_map(enc, &mK, QK16 + nQK, DD, MQKV);
    make_map(enc, &mP, P16, SS, MQKV);
    make_map(enc, &mV, Vt, MQKV, DD);

    cudaFuncSetAttribute(mma_gemm<1>, cudaFuncAttributeMaxDynamicSharedMemorySize, SMEM_TOTAL);
    cudaFuncSetAttribute(mma_gemm<2>, cudaFuncAttributeMaxDynamicSharedMemorySize, SMEM_TOTAL);
    cudaFuncSetAttribute(mma_gemm<3>, cudaFuncAttributeMaxDynamicSharedMemorySize, SMEM_TOTAL);

    const size_t n4x = (size_t)MQKV * DD / 4;
    dim3 tb(32, 8);

    // 1) input conversions (+ zero RS accumulators)
    cudaMemsetAsync(RS, 0, (size_t)MQKV * sizeof(float));
    cast_kernel<<<(unsigned)((n4x + 255) / 256), 256>>>(x, x16, n4x);
    tcast_kernel<<<dim3(DD / 32, DD / 32), tb>>>(WQ, Wt + 0 * nW, DD, DD);
    tcast_kernel<<<dim3(DD / 32, DD / 32), tb>>>(WK, Wt + 1 * nW, DD, DD);
    tcast_kernel<<<dim3(DD / 32, DD / 32), tb>>>(WV, Wt + 2 * nW, DD, DD);

    // 2) all 3 projections in one launch (z: 0=Q fp16, 1=K fp16, 2=V fp32)
    dim3 gp(DD / TN_, MQKV / TM_, 3);                 // 8 x 64 x 3
    mma_gemm<1><<<gp, NT, SMEM_TOTAL>>>(mX, mW,
                                        F, QK16, nullptr,
                                        DD, DD, nQK, 0, DD, 0, 1.0f);
    tcast_kernel<<<dim3(DD / 32, MQKV / 32), tb>>>(F, Vt, MQKV, DD);

    // 3) scores + exp + row-sum fused: P = exp(Q @ K^T / 32), RS += row sums
    dim3 gs(SS / TN_, SS / TM_, BB);                  // 16 x 16 x 4
    mma_gemm<2><<<gs, NT, SMEM_TOTAL>>>(mQ, mK,
                                        nullptr, P16, RS,
                                        DD, SS, (size_t)SS * SS, SS, SS, 0,
                                        1.0f / 32.0f);

    // 4) O = (P @ V^T-rows) / rowsum
    dim3 go(DD / TN_, SS / TM_, BB);                  // 8 x 16 x 4
    mma_gemm<3><<<go, NT, SMEM_TOTAL>>>(mP, mV,
                                        out, nullptr, RS,
                                        SS, DD, (size_t)SS * DD, SS, 0, SS, 1.0f);
}

// round 15
// speedup vs baseline: 4.0157x; 1.0185x over previous
#include <cuda_runtime.h>
#include <cuda.h>
#include <cuda_fp16.h>
#include <cstdint>

// Shapes (fixed): B=4, S=2048, D=1024
#define BB 4
#define SS 2048
#define DD 1024
#define MQKV (BB * SS)            // 8192

// ---- GEMM tile: 128x128, BK=64 (128B rows, SW128), 4 warps, 3 stages,
// ---- 2 CTAs/SM. Stage = A + B = 2 fp16 tiles (32 KB).
#define TM_ 128
#define TN_ 128
#define BK 64
#define A_TILE_B (128 * 128)      // 16384
#define B_TILE_B (128 * 128)      // 16384
#define STAGE_B  (A_TILE_B + B_TILE_B)           // 32768
#define NSTAGE 3
#define SMEM_TOTAL (1024 + NSTAGE * STAGE_B)     // 99328 (x2 CTAs = 198656)
#define NT 128                    // 4 warps
#define TW_STRIDE 40              // transpose buffer stride (halves); conflict-free

// ---------------- scratch (device globals; allocation-free rule) -----------
__device__ __align__(256) __half g_x16[(size_t)MQKV * DD];           // x fp16
__device__ __align__(256) __half g_Wt[(size_t)3 * DD * DD];          // W^T planes
__device__ __align__(256) __half g_QK16[(size_t)2 * MQKV * DD];      // Q,K planes
__device__ __align__(256) __half g_Vt[(size_t)DD * MQKV];            // V^T fp16
__device__ __align__(256) __half g_P16[(size_t)BB * SS * SS];        // exp(S) fp16
__device__ __align__(256) float  g_RS[MQKV];                         // row sums

// ---------------- PTX helpers ----------------------------------------------
__device__ __forceinline__ uint32_t smem_u32(const void* p) {
    uint32_t a;
    asm("{ .reg .u64 t; cvta.to.shared.u64 t, %1; cvt.u32.u64 %0, t; }"
        : "=r"(a) : "l"(p));
    return a;
}
#define LDSM4(r, addr)                                                      \
    asm volatile("ldmatrix.sync.aligned.m8n8.x4.shared.b16 {%0,%1,%2,%3}, [%4];" \
        : "=r"((r)[0]), "=r"((r)[1]), "=r"((r)[2]), "=r"((r)[3]) : "r"(addr))

#define MMA(c, a, b0, b1)                                                   \
    asm volatile("mma.sync.aligned.m16n8k16.row.col.f32.f16.f16.f32 "       \
        "{%0,%1,%2,%3}, {%4,%5,%6,%7}, {%8,%9}, {%0,%1,%2,%3};"             \
        : "+f"((c)[0]), "+f"((c)[1]), "+f"((c)[2]), "+f"((c)[3])            \
        : "r"((a)[0]), "r"((a)[1]), "r"((a)[2]), "r"((a)[3]),               \
          "r"(b0), "r"(b1))

__device__ __forceinline__ void tma2d(uint32_t dst, const void* map,
                                      int x, int y, uint32_t mb) {
    asm volatile(
        "cp.async.bulk.tensor.2d.shared::cta.global.tile.mbarrier::complete_tx::bytes "
        "[%0], [%1, {%2, %3}], [%4];"
        :: "r"(dst), "l"(map), "r"(x), "r"(y), "r"(mb) : "memory");
}
#define MB_INIT(mb, c) \
    asm volatile("mbarrier.init.shared.b64 [%0], %1;" :: "r"(mb), "r"(c) : "memory")
#define MB_EXPECT(mb, bytes) \
    asm volatile("mbarrier.arrive.expect_tx.shared.b64 _, [%0], %1;" \
                 :: "r"(mb), "r"(bytes) : "memory")
#define MB_WAIT(mb, ph) do {                                               \
    asm volatile("{\n\t.reg .pred P;\n\t"                                  \
        "WL%=:\n\t"                                                        \
        "mbarrier.try_wait.parity.acquire.cta.shared::cta.b64 P, [%0], %1;\n\t" \
        "@!P bra WL%=;\n\t}"                                               \
        :: "r"(mb), "r"(ph) : "memory");                                   \
} while (0)

// ---------------------------------------------------------------------------
// Pure fp16 GEMM (fp32 acc):  acc[M,N] = A[M,K] @ B[N,K]^T.
// 1 MMA per k16. TMA pipeline (3 stages, BK=64, SW128), 2 CTAs/SM.
// EPI=1 (projections, z in {0,1,2}): z<2 -> fp16 O16 + z*strideC (Q,K planes)
//                                    z==2 -> fp16 TRANSPOSED into VT [D,MQKV]
// EPI=2 (scores): p = expf(acc*alpha) -> fp16 O16 + z*strideC,
//                 row sums atomically accumulated into RS[z*SS + row]
// EPI=3 (AV):     o = acc / RS[z*SS+row] -> fp32 C + z*strideC
// Grid (N/128, M/128, z). 128 threads, 4 warps of 64x64.
// ---------------------------------------------------------------------------
template <int EPI>
__global__ __launch_bounds__(NT, 2)
void mma_gemm(const __grid_constant__ CUtensorMap mA,
              const __grid_constant__ CUtensorMap mB,
              float* __restrict__ C,
              __half* __restrict__ O16,
              __half* __restrict__ VT,
              float* __restrict__ RS,
              int K, int ldc, size_t strideC,
              int zRowA, int zRowB, int zColB, float alpha)
{
    extern __shared__ char smem[];
    const uint32_t sbase = smem_u32(smem);
    const uint32_t bufs  = (sbase + 1023u) & ~1023u;   // 1024-align
    const uint32_t mbar  = sbase;                      // 3 mbarriers
    const int tid  = threadIdx.x;
    const int lane = tid & 31, wid = tid >> 5;
    const int bz = blockIdx.z;
    const int tileM = blockIdx.y * TM_;
    const int tileN = blockIdx.x * TN_;
    const int rowA0 = tileM + bz * zRowA;
    const int rowB0 = tileN + bz * zRowB;
    const int colB0 = bz * zColB;

    if (tid == 0) {
        #pragma unroll
        for (int i = 0; i < NSTAGE; i++) MB_INIT(mbar + 8 * i, 1);
    }
    __syncthreads();

    const int nst = K / BK;
    auto issue = [&](int slot, int s) {
        const uint32_t buf = bufs + (uint32_t)slot * STAGE_B;
        const uint32_t mb  = mbar + (uint32_t)slot * 8;
        const int kt = s * BK;
        MB_EXPECT(mb, STAGE_B);
        tma2d(buf,            &mA, kt,         rowA0, mb);
        tma2d(buf + A_TILE_B, &mB, kt + colB0, rowB0, mb);
    };
    if (tid == 0) { issue(0, 0); issue(1, 1); }

    const int wm = (wid >> 1) * 64;        // warp M offset (0/64)
    const int wn = (wid & 1) * 64;         // warp N offset (0/64)

    // ldmatrix lane addressing; SW128: xor = (row&7)<<4 on byte column
    uint32_t aoff[4], axor[4], boff[4], bxor[4];
    {
        const int arl = wm + (lane & 15);
        const int brl = wn + (lane & 7) + ((lane >> 4) * 8);
        #pragma unroll
        for (int i = 0; i < 4; i++) {
            int ar = arl + i * 16;
            aoff[i] = (uint32_t)(ar * 128);
            axor[i] = (uint32_t)((ar & 7) << 4);
            int br = brl + i * 16;
            boff[i] = (uint32_t)(br * 128);
            bxor[i] = (uint32_t)((br & 7) << 4);
        }
    }
    const uint32_t a_colb = (uint32_t)((lane >> 4) * 16);
    const uint32_t b_colb = (uint32_t)(((lane >> 3) & 1) * 16);

    float acc[4][8][4];
    #pragma unroll
    for (int i = 0; i < 4; i++)
        #pragma unroll
        for (int j = 0; j < 8; j++)
            #pragma unroll
            for (int r = 0; r < 4; r++) acc[i][j][r] = 0.0f;

    int st = 0, ph = 0, ibuf = 2;
    for (int s = 0; s < nst; s++) {
        const uint32_t buf = bufs + (uint32_t)st * STAGE_B;
        MB_WAIT(mbar + (uint32_t)st * 8, (uint32_t)ph);
        if (tid == 0 && s + 2 < nst) issue(ibuf, s + 2);
        if (++ibuf == NSTAGE) ibuf = 0;

        const uint32_t bufA = buf;
        const uint32_t bufB = buf + A_TILE_B;
        #pragma unroll
        for (int ks = 0; ks < 4; ks++) {
            const uint32_t kb = (uint32_t)(ks * 32);
            uint32_t a[4][4], b[4][4];
            #pragma unroll
            for (int mt = 0; mt < 4; mt++)
                LDSM4(a[mt], bufA + aoff[mt] + ((kb + a_colb) ^ axor[mt]));
            #pragma unroll
            for (int j = 0; j < 4; j++)
                LDSM4(b[j], bufB + boff[j] + ((kb + b_colb) ^ bxor[j]));
            #pragma unroll
            for (int mt = 0; mt < 4; mt++) {
                #pragma unroll
                for (int j = 0; j < 4; j++) {
                    MMA(acc[mt][2 * j],     a[mt], b[j][0], b[j][1]);
                    MMA(acc[mt][2 * j + 1], a[mt], b[j][2], b[j][3]);
                }
            }
        }
        __syncthreads();
        if (++st == NSTAGE) { st = 0; ph ^= 1; }
    }

    // ---- epilogue ----
    const int er = lane >> 2;              // 0..7
    const int ec = (lane & 3) * 2;         // 0,2,4,6

    if (EPI == 1 && bz == 2) {
        // V path: transpose 128x128 tile via per-warp 32x40-half smem buffer,
        // write Vt[D][MQKV] with 64B-contiguous per-lane stores.
        // Pipeline smem is dead here (all stages consumed, syncthreads passed).
        __half* tw = reinterpret_cast<__half*>(
            smem + (bufs - sbase) + (uint32_t)wid * (32 * TW_STRIDE * 2));
        #pragma unroll
        for (int si = 0; si < 2; si++) {
            #pragma unroll
            for (int sj = 0; sj < 2; sj++) {
                #pragma unroll
                for (int mt2 = 0; mt2 < 2; mt2++) {
                    const int mt = 2 * si + mt2;
                    const int r0 = mt2 * 16 + er;
                    #pragma unroll
                    for (int jj = 0; jj < 4; jj++) {
                        const int j  = 4 * sj + jj;
                        const int c0 = jj * 8 + ec;
                        *reinterpret_cast<__half2*>(&tw[r0 * TW_STRIDE + c0]) =
                            __floats2half2_rn(acc[mt][j][0], acc[mt][j][1]);
                        *reinterpret_cast<__half2*>(&tw[(r0 + 8) * TW_STRIDE + c0]) =
                            __floats2half2_rn(acc[mt][j][2], acc[mt][j][3]);
                    }
                }
                __syncwarp();
                uint32_t tmp[16];
                #pragma unroll
                for (int m = 0; m < 32; m += 2) {
                    __half2 pr;
                    pr.x = tw[m * TW_STRIDE + lane];
                    pr.y = tw[(m + 1) * TW_STRIDE + lane];
                    tmp[m >> 1] = *reinterpret_cast<uint32_t*>(&pr);
                }
                const size_t off =
                    (size_t)(tileN + wn + sj * 32 + lane) * (size_t)MQKV
                    + (size_t)(tileM + wm + si * 32);
                uint4* dst = reinterpret_cast<uint4*>(VT + off);
                dst[0] = make_uint4(tmp[0],  tmp[1],  tmp[2],  tmp[3]);
                dst[1] = make_uint4(tmp[4],  tmp[5],  tmp[6],  tmp[7]);
                dst[2] = make_uint4(tmp[8],  tmp[9],  tmp[10], tmp[11]);
                dst[3] = make_uint4(tmp[12], tmp[13], tmp[14], tmp[15]);
                __syncwarp();
            }
        }
        return;
    }

    const bool fp32_path = (EPI == 3);
    float* Cz = (EPI == 3) ? C + (size_t)bz * strideC : C;
    __half* O16z = O16 + (size_t)bz * strideC;
    float* RSz = RS + (size_t)bz * SS;

    #pragma unroll
    for (int mt = 0; mt < 4; mt++) {
        const int rloc = tileM + wm + mt * 16 + er;
        float inv0 = 0.f, inv1 = 0.f;
        if (EPI == 3) { inv0 = 1.0f / RSz[rloc]; inv1 = 1.0f / RSz[rloc + 8]; }
        float rs0 = 0.f, rs1 = 0.f;
        #pragma unroll
        for (int j = 0; j < 8; j++) {
            const int col = tileN + wn + j * 8 + ec;
            float v0 = acc[mt][j][0] * alpha, v1 = acc[mt][j][1] * alpha;
            float v2 = acc[mt][j][2] * alpha, v3 = acc[mt][j][3] * alpha;
            if (EPI == 2) {
                v0 = __expf(v0); v1 = __expf(v1);
                v2 = __expf(v2); v3 = __expf(v3);
                rs0 += v0 + v1;  rs1 += v2 + v3;
            }
            if (EPI == 3) { v0 *= inv0; v1 *= inv0; v2 *= inv1; v3 *= inv1; }
            const size_t o0 = (size_t)rloc * ldc + col;
            const size_t o1 = (size_t)(rloc + 8) * ldc + col;
            if (fp32_path) {
                *reinterpret_cast<float2*>(&Cz[o0]) = make_float2(v0, v1);
                *reinterpret_cast<float2*>(&Cz[o1]) = make_float2(v2, v3);
            } else {
                *reinterpret_cast<__half2*>(&O16z[o0]) = __floats2half2_rn(v0, v1);
                *reinterpret_cast<__half2*>(&O16z[o1]) = __floats2half2_rn(v2, v3);
            }
        }
        if (EPI == 2) {
            rs0 += __shfl_xor_sync(~0u, rs0, 1);
            rs0 += __shfl_xor_sync(~0u, rs0, 2);
            rs1 += __shfl_xor_sync(~0u, rs1, 1);
            rs1 += __shfl_xor_sync(~0u, rs1, 2);
            if ((lane & 3) == 0) {
                atomicAdd(&RSz[rloc], rs0);
                atomicAdd(&RSz[rloc + 8], rs1);
            }
        }
    }
}

// ---------------------------------------------------------------------------
// fp32 -> fp16 cast, elementwise
// ---------------------------------------------------------------------------
__global__ __launch_bounds__(256)
void cast_kernel(const float* __restrict__ in, __half* __restrict__ o16,
                 size_t n4)
{
    size_t i = (size_t)blockIdx.x * blockDim.x + threadIdx.x;
    if (i >= n4) return;
    float4 v = reinterpret_cast<const float4*>(in)[i];
    reinterpret_cast<__half2*>(o16)[2 * i]     = __floats2half2_rn(v.x, v.y);
    reinterpret_cast<__half2*>(o16)[2 * i + 1] = __floats2half2_rn(v.z, v.w);
}

// ---------------------------------------------------------------------------
// fp32 [R,C] -> transposed fp16 [C,R]  (weights only)
// ---------------------------------------------------------------------------
__global__ __launch_bounds__(256)
void tcast_kernel(const float* __restrict__ in, __half* __restrict__ o16,
                  int R, int C)
{
    __shared__ float tile[32][33];
    const int c0 = blockIdx.x * 32, r0 = blockIdx.y * 32;
    const int tx = threadIdx.x, ty = threadIdx.y;   // 32 x 8
    #pragma unroll
    for (int j = 0; j < 32; j += 8)
        tile[ty + j][tx] = in[(size_t)(r0 + ty + j) * C + c0 + tx];
    __syncthreads();
    #pragma unroll
    for (int j = 0; j < 32; j += 8) {
        float v = tile[tx][ty + j];
        o16[(size_t)(c0 + ty + j) * R + r0 + tx] = __float2half_rn(v);
    }
}

// ---------------------------------------------------------------------------
// Host: tensor-map builder (driver entry point, no -lcuda needed)
// ---------------------------------------------------------------------------
typedef CUresult (*PFN_TMAPENC)(CUtensorMap*, CUtensorMapDataType, cuuint32_t,
                                void*, const cuuint64_t*, const cuuint64_t*,
                                const cuuint32_t*, const cuuint32_t*,
                                CUtensorMapInterleave, CUtensorMapSwizzle,
                                CUtensorMapL2promotion, CUtensorMapFloatOOBfill);

static void make_map(PFN_TMAPENC enc, CUtensorMap* m, void* base,
                     unsigned long long cols, unsigned long long rows)
{
    cuuint64_t dims[2]    = {cols, rows};
    cuuint64_t strides[1] = {cols * 2};
    cuuint32_t box[2]     = {64, 128};          // 64 fp16 = 128B rows, 128 rows
    cuuint32_t es[2]      = {1, 1};
    enc(m, CU_TENSOR_MAP_DATA_TYPE_FLOAT16, 2, base, dims, strides, box, es,
        CU_TENSOR_MAP_INTERLEAVE_NONE, CU_TENSOR_MAP_SWIZZLE_128B,
        CU_TENSOR_MAP_L2_PROMOTION_L2_128B, CU_TENSOR_MAP_FLOAT_OOB_FILL_NONE);
}

extern "C" void kernel_launch(void* const* d_in, const int* in_sizes, int n_in,
                              void* d_out, int out_size)
{
    const float* x  = (const float*)d_in[0];
    const float* WQ = (const float*)d_in[1];
    const float* WK = (const float*)d_in[2];
    const float* WV = (const float*)d_in[3];
    float* out = (float*)d_out;

    __half *x16, *Wt, *QK16, *Vt, *P16;
    float *RS;
    cudaGetSymbolAddress((void**)&x16, g_x16);
    cudaGetSymbolAddress((void**)&Wt,  g_Wt);
    cudaGetSymbolAddress((void**)&QK16, g_QK16);
    cudaGetSymbolAddress((void**)&Vt,  g_Vt);
    cudaGetSymbolAddress((void**)&P16, g_P16);
    cudaGetSymbolAddress((void**)&RS,  g_RS);

    const size_t nQK = (size_t)MQKV * DD;       // Q/K plane stride
    const size_t nW  = (size_t)DD * DD;

    PFN_TMAPENC enc = nullptr;
    cudaDriverEntryPointQueryResult qres;
    cudaGetDriverEntryPoint("cuTensorMapEncodeTiled", (void**)&enc,
                            cudaEnableDefault, &qres);

    CUtensorMap mX, mW, mQ, mK, mP, mV;
    make_map(enc, &mX, x16, DD, MQKV);
    make_map(enc, &mW, Wt, DD, 3 * DD);         // 3 weight planes, z-row offset
    make_map(enc, &mQ, QK16, DD, MQKV);
    make_map(enc, &mK, QK16 + nQK, DD, MQKV);
    make_map(enc, &mP, P16, SS, MQKV);
    make_map(enc, &mV, Vt, MQKV, DD);

    cudaFuncSetAttribute(mma_gemm<1>, cudaFuncAttributeMaxDynamicSharedMemorySize, SMEM_TOTAL);
    cudaFuncSetAttribute(mma_gemm<2>, cudaFuncAttributeMaxDynamicSharedMemorySize, SMEM_TOTAL);
    cudaFuncSetAttribute(mma_gemm<3>, cudaFuncAttributeMaxDynamicSharedMemorySize, SMEM_TOTAL);

    const size_t n4x = (size_t)MQKV * DD / 4;
    dim3 tb(32, 8);

    // 1) input conversions (+ zero RS accumulators)
    cudaMemsetAsync(RS, 0, (size_t)MQKV * sizeof(float));
    cast_kernel<<<(unsigned)((n4x + 255) / 256), 256>>>(x, x16, n4x);
    tcast_kernel<<<dim3(DD / 32, DD / 32), tb>>>(WQ, Wt + 0 * nW, DD, DD);
    tcast_kernel<<<dim3(DD / 32, DD / 32), tb>>>(WK, Wt + 1 * nW, DD, DD);
    tcast_kernel<<<dim3(DD / 32, DD / 32), tb>>>(WV, Wt + 2 * nW, DD, DD);

    // 2) all 3 projections in one launch
    //    (z: 0=Q fp16, 1=K fp16, 2=V fp16 transposed in-epilogue)
    dim3 gp(DD / TN_, MQKV / TM_, 3);                 // 8 x 64 x 3
    mma_gemm<1><<<gp, NT, SMEM_TOTAL>>>(mX, mW,
                                        nullptr, QK16, Vt, nullptr,
                                        DD, DD, nQK, 0, DD, 0, 1.0f);

    // 3) scores + exp + row-sum fused: P = exp(Q @ K^T / 32), RS += row sums
    dim3 gs(SS / TN_, SS / TM_, BB);                  // 16 x 16 x 4
    mma_gemm<2><<<gs, NT, SMEM_TOTAL>>>(mQ, mK,
                                        nullptr, P16, nullptr, RS,
                                        DD, SS, (size_t)SS * SS, SS, SS, 0,
                                        1.0f / 32.0f);

    // 4) O = (P @ V^T-rows) / rowsum
    dim3 go(DD / TN_, SS / TM_, BB);                  // 8 x 16 x 4
    mma_gemm<3><<<go, NT, SMEM_TOTAL>>>(mP, mV,
                                        out, nullptr, nullptr, RS,
                                        SS, DD, (size_t)SS * DD, SS, 0, SS, 1.0f);
}

// round 16
// speedup vs baseline: 4.0489x; 1.0083x over previous
#include <cuda_runtime.h>
#include <cuda.h>
#include <cuda_fp16.h>
#include <cstdint>

// Shapes (fixed): B=4, S=2048, D=1024
#define BB 4
#define SS 2048
#define DD 1024
#define MQKV (BB * SS)            // 8192

// ---- GEMM tile: 128x128, BK=64 (128B rows, SW128), 4 warps, 3 stages,
// ---- 2 CTAs/SM. Stage = A + B = 2 fp16 tiles (32 KB).
#define TM_ 128
#define TN_ 128
#define BK 64
#define A_TILE_B (128 * 128)      // 16384
#define B_TILE_B (128 * 128)      // 16384
#define STAGE_B  (A_TILE_B + B_TILE_B)           // 32768
#define NSTAGE 3
#define SMEM_TOTAL (1024 + NSTAGE * STAGE_B)     // 99328 (x2 CTAs = 198656)
#define NT 128                    // 4 warps
#define TW_STRIDE 40              // transpose buffer stride (halves); conflict-free

// ---------------- scratch (device globals; allocation-free rule) -----------
__device__ __align__(256) __half g_x16[(size_t)MQKV * DD];           // x fp16
__device__ __align__(256) __half g_Wt[(size_t)3 * DD * DD];          // W^T planes
__device__ __align__(256) __half g_QK16[(size_t)2 * MQKV * DD];      // Q,K planes
__device__ __align__(256) __half g_Vt[(size_t)DD * MQKV];            // V^T fp16
__device__ __align__(256) __half g_P16[(size_t)BB * SS * SS];        // exp(S) fp16
__device__ __align__(256) float  g_RS[MQKV];                         // row sums

// ---------------- PTX helpers ----------------------------------------------
__device__ __forceinline__ uint32_t smem_u32(const void* p) {
    uint32_t a;
    asm("{ .reg .u64 t; cvta.to.shared.u64 t, %1; cvt.u32.u64 %0, t; }"
        : "=r"(a) : "l"(p));
    return a;
}
#define LDSM4(r, addr)                                                      \
    asm volatile("ldmatrix.sync.aligned.m8n8.x4.shared.b16 {%0,%1,%2,%3}, [%4];" \
        : "=r"((r)[0]), "=r"((r)[1]), "=r"((r)[2]), "=r"((r)[3]) : "r"(addr))

#define MMA(c, a, b0, b1)                                                   \
    asm volatile("mma.sync.aligned.m16n8k16.row.col.f32.f16.f16.f32 "       \
        "{%0,%1,%2,%3}, {%4,%5,%6,%7}, {%8,%9}, {%0,%1,%2,%3};"             \
        : "+f"((c)[0]), "+f"((c)[1]), "+f"((c)[2]), "+f"((c)[3])            \
        : "r"((a)[0]), "r"((a)[1]), "r"((a)[2]), "r"((a)[3]),               \
          "r"(b0), "r"(b1))

__device__ __forceinline__ void tma2d(uint32_t dst, const void* map,
                                      int x, int y, uint32_t mb) {
    asm volatile(
        "cp.async.bulk.tensor.2d.shared::cta.global.tile.mbarrier::complete_tx::bytes "
        "[%0], [%1, {%2, %3}], [%4];"
        :: "r"(dst), "l"(map), "r"(x), "r"(y), "r"(mb) : "memory");
}
#define MB_INIT(mb, c) \
    asm volatile("mbarrier.init.shared.b64 [%0], %1;" :: "r"(mb), "r"(c) : "memory")
#define MB_EXPECT(mb, bytes) \
    asm volatile("mbarrier.arrive.expect_tx.shared.b64 _, [%0], %1;" \
                 :: "r"(mb), "r"(bytes) : "memory")
#define MB_WAIT(mb, ph) do {                                               \
    asm volatile("{\n\t.reg .pred P;\n\t"                                  \
        "WL%=:\n\t"                                                        \
        "mbarrier.try_wait.parity.acquire.cta.shared::cta.b64 P, [%0], %1;\n\t" \
        "@!P bra WL%=;\n\t}"                                               \
        :: "r"(mb), "r"(ph) : "memory");                                   \
} while (0)

// ---------------------------------------------------------------------------
// Pure fp16 GEMM (fp32 acc):  acc[M,N] = A[M,K] @ B[N,K]^T.
// 1 MMA per k16. TMA pipeline (3 stages, BK=64, SW128), 2 CTAs/SM.
// EPI=1 (projections, z in {0,1,2}): z<2 -> fp16 O16 + z*strideC (Q,K planes)
//                                    z==2 -> fp16 TRANSPOSED into VT [D,MQKV]
// EPI=2 (scores): p = expf(acc*alpha) -> fp16 O16 + z*strideC,
//                 row sums atomically accumulated into RS[z*SS + row]
// EPI=3 (AV):     o = acc / RS[z*SS+row] -> fp32 C + z*strideC
// Grid (N/128, M/128, z). 128 threads, 4 warps of 64x64.
// ---------------------------------------------------------------------------
template <int EPI>
__global__ __launch_bounds__(NT, 2)
void mma_gemm(const __grid_constant__ CUtensorMap mA,
              const __grid_constant__ CUtensorMap mB,
              float* __restrict__ C,
              __half* __restrict__ O16,
              __half* __restrict__ VT,
              float* __restrict__ RS,
              int K, int ldc, size_t strideC,
              int zRowA, int zRowB, int zColB, float alpha)
{
    extern __shared__ char smem[];
    const uint32_t sbase = smem_u32(smem);
    const uint32_t bufs  = (sbase + 1023u) & ~1023u;   // 1024-align
    const uint32_t mbar  = sbase;                      // 3 mbarriers
    const int tid  = threadIdx.x;
    const int lane = tid & 31, wid = tid >> 5;
    const int bz = blockIdx.z;
    const int tileM = blockIdx.y * TM_;
    const int tileN = blockIdx.x * TN_;
    const int rowA0 = tileM + bz * zRowA;
    const int rowB0 = tileN + bz * zRowB;
    const int colB0 = bz * zColB;

    if (tid == 0) {
        #pragma unroll
        for (int i = 0; i < NSTAGE; i++) MB_INIT(mbar + 8 * i, 1);
    }
    __syncthreads();

    const int nst = K / BK;
    auto issue = [&](int slot, int s) {
        const uint32_t buf = bufs + (uint32_t)slot * STAGE_B;
        const uint32_t mb  = mbar + (uint32_t)slot * 8;
        const int kt = s * BK;
        MB_EXPECT(mb, STAGE_B);
        tma2d(buf,            &mA, kt,         rowA0, mb);
        tma2d(buf + A_TILE_B, &mB, kt + colB0, rowB0, mb);
    };
    if (tid == 0) { issue(0, 0); issue(1, 1); }

    const int wm = (wid >> 1) * 64;        // warp M offset (0/64)
    const int wn = (wid & 1) * 64;         // warp N offset (0/64)

    // ldmatrix lane addressing; SW128: xor = (row&7)<<4 on byte column
    uint32_t aoff[4], axor[4], boff[4], bxor[4];
    {
        const int arl = wm + (lane & 15);
        const int brl = wn + (lane & 7) + ((lane >> 4) * 8);
        #pragma unroll
        for (int i = 0; i < 4; i++) {
            int ar = arl + i * 16;
            aoff[i] = (uint32_t)(ar * 128);
            axor[i] = (uint32_t)((ar & 7) << 4);
            int br = brl + i * 16;
            boff[i] = (uint32_t)(br * 128);
            bxor[i] = (uint32_t)((br & 7) << 4);
        }
    }
    const uint32_t a_colb = (uint32_t)((lane >> 4) * 16);
    const uint32_t b_colb = (uint32_t)(((lane >> 3) & 1) * 16);

    float acc[4][8][4];
    #pragma unroll
    for (int i = 0; i < 4; i++)
        #pragma unroll
        for (int j = 0; j < 8; j++)
            #pragma unroll
            for (int r = 0; r < 4; r++) acc[i][j][r] = 0.0f;

    int st = 0, ph = 0, ibuf = 2;
    for (int s = 0; s < nst; s++) {
        const uint32_t buf = bufs + (uint32_t)st * STAGE_B;
        MB_WAIT(mbar + (uint32_t)st * 8, (uint32_t)ph);
        if (tid == 0 && s + 2 < nst) issue(ibuf, s + 2);
        if (++ibuf == NSTAGE) ibuf = 0;

        const uint32_t bufA = buf;
        const uint32_t bufB = buf + A_TILE_B;
        #pragma unroll
        for (int ks = 0; ks < 4; ks++) {
            const uint32_t kb = (uint32_t)(ks * 32);
            uint32_t a[4][4], b[4][4];
            #pragma unroll
            for (int mt = 0; mt < 4; mt++)
                LDSM4(a[mt], bufA + aoff[mt] + ((kb + a_colb) ^ axor[mt]));
            #pragma unroll
            for (int j = 0; j < 4; j++)
                LDSM4(b[j], bufB + boff[j] + ((kb + b_colb) ^ bxor[j]));
            #pragma unroll
            for (int mt = 0; mt < 4; mt++) {
                #pragma unroll
                for (int j = 0; j < 4; j++) {
                    MMA(acc[mt][2 * j],     a[mt], b[j][0], b[j][1]);
                    MMA(acc[mt][2 * j + 1], a[mt], b[j][2], b[j][3]);
                }
            }
        }
        __syncthreads();
        if (++st == NSTAGE) { st = 0; ph ^= 1; }
    }

    // ---- epilogue ----
    const int er = lane >> 2;              // 0..7
    const int ec = (lane & 3) * 2;         // 0,2,4,6

    if (EPI == 1 && bz == 2) {
        // V path: transpose 128x128 tile via per-warp 32x40-half smem buffer,
        // write Vt[D][MQKV] with 64B-contiguous per-lane stores.
        __half* tw = reinterpret_cast<__half*>(
            smem + (bufs - sbase) + (uint32_t)wid * (32 * TW_STRIDE * 2));
        #pragma unroll
        for (int si = 0; si < 2; si++) {
            #pragma unroll
            for (int sj = 0; sj < 2; sj++) {
                #pragma unroll
                for (int mt2 = 0; mt2 < 2; mt2++) {
                    const int mt = 2 * si + mt2;
                    const int r0 = mt2 * 16 + er;
                    #pragma unroll
                    for (int jj = 0; jj < 4; jj++) {
                        const int j  = 4 * sj + jj;
                        const int c0 = jj * 8 + ec;
                        *reinterpret_cast<__half2*>(&tw[r0 * TW_STRIDE + c0]) =
                            __floats2half2_rn(acc[mt][j][0], acc[mt][j][1]);
                        *reinterpret_cast<__half2*>(&tw[(r0 + 8) * TW_STRIDE + c0]) =
                            __floats2half2_rn(acc[mt][j][2], acc[mt][j][3]);
                    }
                }
                __syncwarp();
                uint32_t tmp[16];
                #pragma unroll
                for (int m = 0; m < 32; m += 2) {
                    __half2 pr;
                    pr.x = tw[m * TW_STRIDE + lane];
                    pr.y = tw[(m + 1) * TW_STRIDE + lane];
                    tmp[m >> 1] = *reinterpret_cast<uint32_t*>(&pr);
                }
                const size_t off =
                    (size_t)(tileN + wn + sj * 32 + lane) * (size_t)MQKV
                    + (size_t)(tileM + wm + si * 32);
                uint4* dst = reinterpret_cast<uint4*>(VT + off);
                dst[0] = make_uint4(tmp[0],  tmp[1],  tmp[2],  tmp[3]);
                dst[1] = make_uint4(tmp[4],  tmp[5],  tmp[6],  tmp[7]);
                dst[2] = make_uint4(tmp[8],  tmp[9],  tmp[10], tmp[11]);
                dst[3] = make_uint4(tmp[12], tmp[13], tmp[14], tmp[15]);
                __syncwarp();
            }
        }
        return;
    }

    const bool fp32_path = (EPI == 3);
    float* Cz = (EPI == 3) ? C + (size_t)bz * strideC : C;
    __half* O16z = O16 + (size_t)bz * strideC;
    float* RSz = RS + (size_t)bz * SS;

    #pragma unroll
    for (int mt = 0; mt < 4; mt++) {
        const int rloc = tileM + wm + mt * 16 + er;
        float inv0 = 0.f, inv1 = 0.f;
        if (EPI == 3) { inv0 = 1.0f / RSz[rloc]; inv1 = 1.0f / RSz[rloc + 8]; }
        float rs0 = 0.f, rs1 = 0.f;
        #pragma unroll
        for (int j = 0; j < 8; j++) {
            const int col = tileN + wn + j * 8 + ec;
            float v0 = acc[mt][j][0] * alpha, v1 = acc[mt][j][1] * alpha;
            float v2 = acc[mt][j][2] * alpha, v3 = acc[mt][j][3] * alpha;
            if (EPI == 2) {
                v0 = __expf(v0); v1 = __expf(v1);
                v2 = __expf(v2); v3 = __expf(v3);
                rs0 += v0 + v1;  rs1 += v2 + v3;
            }
            if (EPI == 3) { v0 *= inv0; v1 *= inv0; v2 *= inv1; v3 *= inv1; }
            const size_t o0 = (size_t)rloc * ldc + col;
            const size_t o1 = (size_t)(rloc + 8) * ldc + col;
            if (fp32_path) {
                *reinterpret_cast<float2*>(&Cz[o0]) = make_float2(v0, v1);
                *reinterpret_cast<float2*>(&Cz[o1]) = make_float2(v2, v3);
            } else {
                *reinterpret_cast<__half2*>(&O16z[o0]) = __floats2half2_rn(v0, v1);
                *reinterpret_cast<__half2*>(&O16z[o1]) = __floats2half2_rn(v2, v3);
            }
        }
        if (EPI == 2) {
            rs0 += __shfl_xor_sync(~0u, rs0, 1);
            rs0 += __shfl_xor_sync(~0u, rs0, 2);
            rs1 += __shfl_xor_sync(~0u, rs1, 1);
            rs1 += __shfl_xor_sync(~0u, rs1, 2);
            if ((lane & 3) == 0) {
                atomicAdd(&RSz[rloc], rs0);
                atomicAdd(&RSz[rloc + 8], rs1);
            }
        }
    }
}

// ---------------------------------------------------------------------------
// fp32 -> fp16 cast, elementwise; also zeroes the RS accumulators.
// ---------------------------------------------------------------------------
__global__ __launch_bounds__(256)
void cast_kernel(const float* __restrict__ in, __half* __restrict__ o16,
                 float* __restrict__ RS, size_t n4)
{
    size_t i = (size_t)blockIdx.x * blockDim.x + threadIdx.x;
    if (i < (size_t)MQKV / 4)
        reinterpret_cast<float4*>(RS)[i] = make_float4(0.f, 0.f, 0.f, 0.f);
    if (i >= n4) return;
    float4 v = reinterpret_cast<const float4*>(in)[i];
    reinterpret_cast<__half2*>(o16)[2 * i]     = __floats2half2_rn(v.x, v.y);
    reinterpret_cast<__half2*>(o16)[2 * i + 1] = __floats2half2_rn(v.z, v.w);
}

// ---------------------------------------------------------------------------
// Three weight matrices [D,D] -> transposed fp16 planes of Wt (z-selected)
// ---------------------------------------------------------------------------
__global__ __launch_bounds__(256)
void tcastW_kernel(const float* __restrict__ W0, const float* __restrict__ W1,
                   const float* __restrict__ W2, __half* __restrict__ o16)
{
    __shared__ float tile[32][33];
    const float* in = (blockIdx.z == 0) ? W0 : (blockIdx.z == 1) ? W1 : W2;
    __half* out = o16 + (size_t)blockIdx.z * DD * DD;
    const int c0 = blockIdx.x * 32, r0 = blockIdx.y * 32;
    const int tx = threadIdx.x, ty = threadIdx.y;   // 32 x 8
    #pragma unroll
    for (int j = 0; j < 32; j += 8)
        tile[ty + j][tx] = in[(size_t)(r0 + ty + j) * DD + c0 + tx];
    __syncthreads();
    #pragma unroll
    for (int j = 0; j < 32; j += 8) {
        float v = tile[tx][ty + j];
        out[(size_t)(c0 + ty + j) * DD + r0 + tx] = __float2half_rn(v);
    }
}

// ---------------------------------------------------------------------------
// Host: tensor-map builder (driver entry point, no -lcuda needed)
// ---------------------------------------------------------------------------
typedef CUresult (*PFN_TMAPENC)(CUtensorMap*, CUtensorMapDataType, cuuint32_t,
                                void*, const cuuint64_t*, const cuuint64_t*,
                                const cuuint32_t*, const cuuint32_t*,
                                CUtensorMapInterleave, CUtensorMapSwizzle,
                                CUtensorMapL2promotion, CUtensorMapFloatOOBfill);

static void make_map(PFN_TMAPENC enc, CUtensorMap* m, void* base,
                     unsigned long long cols, unsigned long long rows)
{
    cuuint64_t dims[2]    = {cols, rows};
    cuuint64_t strides[1] = {cols * 2};
    cuuint32_t box[2]     = {64, 128};          // 64 fp16 = 128B rows, 128 rows
    cuuint32_t es[2]      = {1, 1};
    enc(m, CU_TENSOR_MAP_DATA_TYPE_FLOAT16, 2, base, dims, strides, box, es,
        CU_TENSOR_MAP_INTERLEAVE_NONE, CU_TENSOR_MAP_SWIZZLE_128B,
        CU_TENSOR_MAP_L2_PROMOTION_L2_128B, CU_TENSOR_MAP_FLOAT_OOB_FILL_NONE);
}

extern "C" void kernel_launch(void* const* d_in, const int* in_sizes, int n_in,
                              void* d_out, int out_size)
{
    const float* x  = (const float*)d_in[0];
    const float* WQ = (const float*)d_in[1];
    const float* WK = (const float*)d_in[2];
    const float* WV = (const float*)d_in[3];
    float* out = (float*)d_out;

    __half *x16, *Wt, *QK16, *Vt, *P16;
    float *RS;
    cudaGetSymbolAddress((void**)&x16, g_x16);
    cudaGetSymbolAddress((void**)&Wt,  g_Wt);
    cudaGetSymbolAddress((void**)&QK16, g_QK16);
    cudaGetSymbolAddress((void**)&Vt,  g_Vt);
    cudaGetSymbolAddress((void**)&P16, g_P16);
    cudaGetSymbolAddress((void**)&RS,  g_RS);

    const size_t nQK = (size_t)MQKV * DD;       // Q/K plane stride

    PFN_TMAPENC enc = nullptr;
    cudaDriverEntryPointQueryResult qres;
    cudaGetDriverEntryPoint("cuTensorMapEncodeTiled", (void**)&enc,
                            cudaEnableDefault, &qres);

    CUtensorMap mX, mW, mQ, mK, mP, mV;
    make_map(enc, &mX, x16, DD, MQKV);
    make_map(enc, &mW, Wt, DD, 3 * DD);         // 3 weight planes, z-row offset
    make_map(enc, &mQ, QK16, DD, MQKV);
    make_map(enc, &mK, QK16 + nQK, DD, MQKV);
    make_map(enc, &mP, P16, SS, MQKV);
    make_map(enc, &mV, Vt, MQKV, DD);

    cudaFuncSetAttribute(mma_gemm<1>, cudaFuncAttributeMaxDynamicSharedMemorySize, SMEM_TOTAL);
    cudaFuncSetAttribute(mma_gemm<2>, cudaFuncAttributeMaxDynamicSharedMemorySize, SMEM_TOTAL);
    cudaFuncSetAttribute(mma_gemm<3>, cudaFuncAttributeMaxDynamicSharedMemorySize, SMEM_TOTAL);

    const size_t n4x = (size_t)MQKV * DD / 4;
    dim3 tb(32, 8);

    // 1) input conversions (x cast + RS zero; all 3 weights in one launch)
    cast_kernel<<<(unsigned)((n4x + 255) / 256), 256>>>(x, x16, RS, n4x);
    tcastW_kernel<<<dim3(DD / 32, DD / 32, 3), tb>>>(WQ, WK, WV, Wt);

    // 2) all 3 projections in one launch
    //    (z: 0=Q fp16, 1=K fp16, 2=V fp16 transposed in-epilogue)
    dim3 gp(DD / TN_, MQKV / TM_, 3);                 // 8 x 64 x 3
    mma_gemm<1><<<gp, NT, SMEM_TOTAL>>>(mX, mW,
                                        nullptr, QK16, Vt, nullptr,
                                        DD, DD, nQK, 0, DD, 0, 1.0f);

    // 3) scores + exp + row-sum fused: P = exp(Q @ K^T / 32), RS += row sums
    dim3 gs(SS / TN_, SS / TM_, BB);                  // 16 x 16 x 4
    mma_gemm<2><<<gs, NT, SMEM_TOTAL>>>(mQ, mK,
                                        nullptr, P16, nullptr, RS,
                                        DD, SS, (size_t)SS * SS, SS, SS, 0,
                                        1.0f / 32.0f);

    // 4) O = (P @ V^T-rows) / rowsum
    dim3 go(DD / TN_, SS / TM_, BB);                  // 8 x 16 x 4
    mma_gemm<3><<<go, NT, SMEM_TOTAL>>>(mP, mV,
                                        out, nullptr, nullptr, RS,
                                        SS, DD, (size_t)SS * DD, SS, 0, SS, 1.0f);
}